// round 4
// baseline (speedup 1.0000x reference)
#include <cuda_runtime.h>
#include <math.h>
#include <stdint.h>

typedef unsigned long long ull;

// Problem constants
#define NB 32
#define C 128
#define HW 4096
#define K 64
#define KE 56
#define TP 128
#define NTILES (HW / TP)   // 32
#define NTHR 512

#define XS_STRIDE 130      // 130 % 32 == 2 -> 2-phase (min) wide LDS.64 column access
#define WT_STRIDE 68       // 68*4 % 16 == 0 -> 16B-aligned rows for bcast LDS.128
#define LS_STRIDE 132      // 132*4 % 16 == 0 -> 16B-aligned rows for bcast LDS.128

// Dynamic smem layout (floats)
#define XS_OFF 0
#define XS_SZ  (C * XS_STRIDE)          // 16640
#define WT_OFF (XS_OFF + XS_SZ)
#define WT_SZ  (C * WT_STRIDE)          // 8704
#define LS_OFF (WT_OFF + WT_SZ)
#define LS_SZ  (K * LS_STRIDE)          // 8448
#define SMEM_FLOATS (LS_OFF + LS_SZ)    // 33792
#define SMEM_BYTES  (SMEM_FLOATS * 4)   // 135168

// Per-(n,tile) partial scratch -- unique slots, plain stores, no atomics, no zeroing
__device__ float g_part[NB * NTILES * KE * C];   // 29.36 MB
__device__ float g_asum_part[NB * NTILES * KE];  // 229 KB

// ---- f32x2 helpers ----
__device__ __forceinline__ ull ffma2(ull a, ull b, ull c) {
    ull d;
    asm("fma.rn.f32x2 %0, %1, %2, %3;" : "=l"(d) : "l"(a), "l"(b), "l"(c));
    return d;
}
__device__ __forceinline__ ull dup2(float v) {
    ull d;
    unsigned u = __float_as_uint(v);
    asm("mov.b64 %0, {%1, %1};" : "=l"(d) : "r"(u));
    return d;
}
__device__ __forceinline__ void unpack2(ull v, float& lo, float& hi) {
    unsigned a, b;
    asm("mov.b64 {%0, %1}, %2;" : "=r"(a), "=r"(b) : "l"(v));
    lo = __uint_as_float(a);
    hi = __uint_as_float(b);
}
__device__ __forceinline__ float f2sum(ull v) {
    float lo, hi;
    unpack2(v, lo, hi);
    return lo + hi;
}

__global__ __launch_bounds__(NTHR, 1)
void netvlad_main(const float* __restrict__ x,
                  const float* __restrict__ conv_w,
                  const float* __restrict__ conv_b) {
    extern __shared__ float sm[];
    float* xs = sm + XS_OFF;   // [C][XS_STRIDE]  raw x tile
    float* wt = sm + WT_OFF;   // [C][WT_STRIDE]  W^T (k contiguous)
    float* ls = sm + LS_OFF;   // [K][LS_STRIDE]  logits -> assignments

    __shared__ float red4[4 * TP];
    __shared__ float rn[TP];
    __shared__ float sinv[TP];
    __shared__ float bs[K];

    const int n    = blockIdx.x;
    const int tile = blockIdx.y;
    const int tid  = threadIdx.x;
    const int lane = tid & 31;
    const int w    = tid >> 5;

    // ---- Load W transposed: wt[c][k] = conv_w[k][c]; bias ----
    for (int idx = tid; idx < K * C; idx += NTHR) {
        int k = idx >> 7, c = idx & 127;
        wt[c * WT_STRIDE + k] = __ldg(conv_w + idx);
    }
    if (tid < K) bs[tid] = conv_b[tid];

    // ---- Load raw x tile: GMEM [c][p] -> xs[c][p] ----
    const float* xt = x + (size_t)n * C * HW + tile * TP;
    for (int idx = tid; idx < C * (TP / 4); idx += NTHR) {
        int c = idx >> 5, p4 = idx & 31;
        float4 v = __ldg((const float4*)(xt + (size_t)c * HW) + p4);
        float* dst = xs + c * XS_STRIDE + p4 * 4;
        *(ull*)(dst)     = *(ull*)&v.x;
        *(ull*)(dst + 2) = *(ull*)&v.z;
    }
    __syncthreads();

    // ---- Sum of squares per pixel -> rn (4 c-segments x 128 p) ----
    {
        const int p = tid & 127, seg = tid >> 7;
        float ss = 0.0f;
        const int c0 = seg * 32;
#pragma unroll 8
        for (int i = 0; i < 32; ++i) {
            float v = xs[(c0 + i) * XS_STRIDE + p];
            ss += v * v;
        }
        red4[seg * TP + p] = ss;
        __syncthreads();
        if (tid < TP) {
            float tot = red4[tid] + red4[TP + tid] + red4[2 * TP + tid] + red4[3 * TP + tid];
            rn[tid] = 1.0f / fmaxf(sqrtf(tot), 1e-12f);
        }
        __syncthreads();
    }

    // ---- GEMM1: logits (k-paired f32x2). warp -> (8 k, 64 p) ----
    {
        const int kb = (w >> 1) * 8;
        const int pb = (w & 1) * 64 + lane;
        ull acc[4][2];
#pragma unroll
        for (int i = 0; i < 4; ++i) { acc[i][0] = 0ull; acc[i][1] = 0ull; }

#pragma unroll 2
        for (int c = 0; c < C; ++c) {
            const float* wr = wt + c * WT_STRIDE + kb;
            ulonglong2 wv0 = *(const ulonglong2*)(wr);      // k pairs (kb,kb+1),(kb+2,kb+3)
            ulonglong2 wv1 = *(const ulonglong2*)(wr + 4);  // (kb+4,kb+5),(kb+6,kb+7)
            ull xd0 = dup2(xs[c * XS_STRIDE + pb]);
            ull xd1 = dup2(xs[c * XS_STRIDE + pb + 32]);
            acc[0][0] = ffma2(wv0.x, xd0, acc[0][0]);
            acc[1][0] = ffma2(wv0.y, xd0, acc[1][0]);
            acc[2][0] = ffma2(wv1.x, xd0, acc[2][0]);
            acc[3][0] = ffma2(wv1.y, xd0, acc[3][0]);
            acc[0][1] = ffma2(wv0.x, xd1, acc[0][1]);
            acc[1][1] = ffma2(wv0.y, xd1, acc[1][1]);
            acc[2][1] = ffma2(wv1.x, xd1, acc[2][1]);
            acc[3][1] = ffma2(wv1.y, xd1, acc[3][1]);
        }
        // epilogue: ls[k][p] = dot * rn[p] + b[k]
        float rn0 = rn[pb], rn1 = rn[pb + 32];
#pragma unroll
        for (int kp = 0; kp < 4; ++kp) {
            int k0 = kb + 2 * kp;
            float b0 = bs[k0], b1 = bs[k0 + 1];
            float lo, hi;
            unpack2(acc[kp][0], lo, hi);
            ls[k0 * LS_STRIDE + pb]       = lo * rn0 + b0;
            ls[(k0 + 1) * LS_STRIDE + pb] = hi * rn0 + b1;
            unpack2(acc[kp][1], lo, hi);
            ls[k0 * LS_STRIDE + pb + 32]       = lo * rn1 + b0;
            ls[(k0 + 1) * LS_STRIDE + pb + 32] = hi * rn1 + b1;
        }
    }
    __syncthreads();

    // ---- Softmax over k per pixel (4 k-quarters x 128 p) ----
    {
        const int p = tid & 127, q = tid >> 7;
        const int k0 = q * 16;
        float m = -1e30f;
#pragma unroll 8
        for (int i = 0; i < 16; ++i) m = fmaxf(m, ls[(k0 + i) * LS_STRIDE + p]);
        red4[q * TP + p] = m;
        __syncthreads();
        float M = fmaxf(fmaxf(red4[p], red4[TP + p]), fmaxf(red4[2 * TP + p], red4[3 * TP + p]));
        __syncthreads();
        float s = 0.0f;
#pragma unroll 8
        for (int i = 0; i < 16; ++i) {
            float e = __expf(ls[(k0 + i) * LS_STRIDE + p] - M);
            ls[(k0 + i) * LS_STRIDE + p] = e;
            s += e;
        }
        red4[q * TP + p] = s;
        __syncthreads();
        if (tid < TP)
            sinv[tid] = 1.0f / (red4[tid] + red4[TP + tid] + red4[2 * TP + tid] + red4[3 * TP + tid]);
        __syncthreads();
    }

    // ---- asum (a = e*sinv) + fold rn into assignments (a' = a*rn); 14 warps x 4 k ----
    if (w < 14) {
        const int kb = w * 4;
        float si[4], sir[4];
#pragma unroll
        for (int j = 0; j < 4; ++j) {
            int p = lane + 32 * j;
            si[j] = sinv[p];
            sir[j] = si[j] * rn[p];
        }
#pragma unroll
        for (int i = 0; i < 4; ++i) {
            float sv = 0.0f;
#pragma unroll
            for (int j = 0; j < 4; ++j) {
                float* ap = ls + (kb + i) * LS_STRIDE + lane + 32 * j;
                float e = *ap;
                sv += e * si[j];
                *ap = e * sir[j];
            }
#pragma unroll
            for (int off = 16; off; off >>= 1) sv += __shfl_down_sync(0xffffffffu, sv, off);
            if (lane == 0)
                g_asum_part[(n * NTILES + tile) * KE + kb + i] = sv;
        }
    }
    __syncthreads();

    // ---- GEMM2: vlad partial (p-paired f32x2). warp -> (7 k, 64 c) ----
    {
        const int kb = (w >> 1) * 7;
        const int cb = (w & 1) * 64 + lane;
        ull vacc[7][2];
#pragma unroll
        for (int i = 0; i < 7; ++i) { vacc[i][0] = 0ull; vacc[i][1] = 0ull; }

        const float* ap0 = ls + kb * LS_STRIDE;
        const float* xv0 = xs + cb * XS_STRIDE;
        const float* xv1 = xs + (cb + 32) * XS_STRIDE;
#pragma unroll 2
        for (int p4 = 0; p4 < TP / 4; ++p4) {
            ulonglong2 a2[7];
#pragma unroll
            for (int i = 0; i < 7; ++i)
                a2[i] = *(const ulonglong2*)(ap0 + i * LS_STRIDE + 4 * p4);  // bcast .128
            ull x00 = *(const ull*)(xv0 + 4 * p4);
            ull x01 = *(const ull*)(xv0 + 4 * p4 + 2);
            ull x10 = *(const ull*)(xv1 + 4 * p4);
            ull x11 = *(const ull*)(xv1 + 4 * p4 + 2);
#pragma unroll
            for (int i = 0; i < 7; ++i) {
                vacc[i][0] = ffma2(a2[i].x, x00, vacc[i][0]);
                vacc[i][0] = ffma2(a2[i].y, x01, vacc[i][0]);
                vacc[i][1] = ffma2(a2[i].x, x10, vacc[i][1]);
                vacc[i][1] = ffma2(a2[i].y, x11, vacc[i][1]);
            }
        }
        // flush partials: plain stores to unique slot
        float* gp = g_part + ((size_t)(n * NTILES + tile) * KE + kb) * C;
#pragma unroll
        for (int i = 0; i < 7; ++i) {
            gp[i * C + cb]      = f2sum(vacc[i][0]);
            gp[i * C + cb + 32] = f2sum(vacc[i][1]);
        }
    }
}

__global__ __launch_bounds__(256)
void netvlad_finalize(const float* __restrict__ centroids, float* __restrict__ out) {
    __shared__ float ys[KE * C];       // 28 KB
    __shared__ float colss[8 * C];     // 4 KB
    __shared__ float colinv[C];
    __shared__ float asl[KE];
    __shared__ float red[8];
    __shared__ float s_inv2;

    const int n = blockIdx.x;
    const int tid = threadIdx.x;

    // asum totals over 32 tiles
    if (tid < KE) {
        float s = 0.0f;
        const float* ap = g_asum_part + (size_t)n * NTILES * KE + tid;
#pragma unroll 8
        for (int t = 0; t < NTILES; ++t) s += ap[t * KE];
        asl[tid] = s;
    }

    // vlad totals over 32 tiles (7 float4 elements per thread)
    float4 s[7];
#pragma unroll
    for (int r = 0; r < 7; ++r) {
        int e4 = tid + r * 256;
        const float* bp = g_part + (size_t)n * NTILES * KE * C + e4 * 4;
        float4 acc = make_float4(0.f, 0.f, 0.f, 0.f);
#pragma unroll 8
        for (int t = 0; t < NTILES; ++t) {
            float4 v = *(const float4*)(bp + (size_t)t * KE * C);
            acc.x += v.x; acc.y += v.y; acc.z += v.z; acc.w += v.w;
        }
        s[r] = acc;
    }
    __syncthreads();

    // subtract a_sum * centroid, store ys, accumulate per-column ssq
    const int cg = (tid & 31) * 4;  // fixed 4-c group per thread
    float4 ss4 = make_float4(0.f, 0.f, 0.f, 0.f);
#pragma unroll
    for (int r = 0; r < 7; ++r) {
        int e4 = tid + r * 256;
        int k = e4 >> 5;
        float a = asl[k];
        float4 ce = *(const float4*)(centroids + k * C + cg);
        float4 y;
        y.x = s[r].x - a * ce.x;
        y.y = s[r].y - a * ce.y;
        y.z = s[r].z - a * ce.z;
        y.w = s[r].w - a * ce.w;
        *(float4*)(ys + k * C + cg) = y;
        ss4.x += y.x * y.x; ss4.y += y.y * y.y;
        ss4.z += y.z * y.z; ss4.w += y.w * y.w;
    }
    *(float4*)(colss + (tid >> 5) * C + cg) = ss4;
    __syncthreads();

    float gs = 0.0f;
    if (tid < C) {
        float cs = 0.0f;
#pragma unroll
        for (int g = 0; g < 8; ++g) cs += colss[g * C + tid];
        float i1 = 1.0f / fmaxf(sqrtf(cs), 1e-12f);
        gs = cs * i1 * i1;
        colinv[tid] = i1;
    }
    __syncthreads();
#pragma unroll
    for (int off = 16; off; off >>= 1) gs += __shfl_down_sync(0xffffffffu, gs, off);
    if ((tid & 31) == 0) red[tid >> 5] = gs;
    __syncthreads();
    if (tid == 0) {
        float t = red[0] + red[1] + red[2] + red[3];
        s_inv2 = 1.0f / fmaxf(sqrtf(t), 1e-12f);
    }
    __syncthreads();
    const float inv2 = s_inv2;
    float* op = out + (size_t)n * KE * C;
    for (int idx = tid; idx < KE * C; idx += 256)
        op[idx] = ys[idx] * colinv[idx & 127] * inv2;
}

extern "C" void kernel_launch(void* const* d_in, const int* in_sizes, int n_in,
                              void* d_out, int out_size) {
    const float* x      = (const float*)d_in[0];
    const float* conv_w = (const float*)d_in[1];
    const float* conv_b = (const float*)d_in[2];
    const float* cen    = (const float*)d_in[3];
    float* out = (float*)d_out;

    cudaFuncSetAttribute(netvlad_main, cudaFuncAttributeMaxDynamicSharedMemorySize, SMEM_BYTES);

    netvlad_main<<<dim3(NB, NTILES), NTHR, SMEM_BYTES>>>(x, conv_w, conv_b);
    netvlad_finalize<<<NB, 256>>>(cen, out);
}

// round 7
// speedup vs baseline: 1.7966x; 1.7966x over previous
#include <cuda_runtime.h>
#include <cuda_fp16.h>
#include <math.h>
#include <stdint.h>

typedef unsigned long long ull;

#define NB 32
#define C 128
#define HW 4096
#define K 64
#define KE 56
#define TP 128
#define NTILES 32
#define NTHR 512

#define RB 272            // row bytes (136 halfs); 272%16==0, 4-bank row shift
#define LS_STRIDE 132     // fp32 logits row stride

// dynamic smem byte offsets
#define XT_HI 0           // xT[p][c] hi   128*272 = 34816
#define XT_LO 34816       // xT[p][c] lo ; overlaid by ls (64*132*4=33792) after GEMM1
#define X_HI  69632       // x[c][p] hi
#define X_LO  104448      // x[c][p] lo
#define W_HI  139264      // W[k][c] hi    64*272 = 17408
#define W_LO  156672
#define A_HI  174080      // a'[k][p] hi
#define A_LO  191488
#define SMEM_DYN 208896

__device__ float g_part[NB * NTILES * K * C];    // per-(n,tile) D2[k][c]
__device__ float g_asum_part[NB * NTILES * K];
__device__ float g_vlad[NB * K * C];

__device__ __forceinline__ uint32_t smem_u32(const void* p) {
    uint32_t a;
    asm("{ .reg .u64 t; cvta.to.shared.u64 t, %1; cvt.u32.u64 %0, t; }" : "=r"(a) : "l"(p));
    return a;
}
__device__ __forceinline__ void ldsm_x4(uint32_t a, uint32_t* r) {
    asm volatile("ldmatrix.sync.aligned.m8n8.x4.shared.b16 {%0,%1,%2,%3}, [%4];"
                 : "=r"(r[0]), "=r"(r[1]), "=r"(r[2]), "=r"(r[3]) : "r"(a));
}
__device__ __forceinline__ void mma16816(float* d, const uint32_t* a, uint32_t b0, uint32_t b1) {
    asm volatile("mma.sync.aligned.m16n8k16.row.col.f32.f16.f16.f32 "
                 "{%0,%1,%2,%3}, {%4,%5,%6,%7}, {%8,%9}, {%0,%1,%2,%3};"
                 : "+f"(d[0]), "+f"(d[1]), "+f"(d[2]), "+f"(d[3])
                 : "r"(a[0]), "r"(a[1]), "r"(a[2]), "r"(a[3]), "r"(b0), "r"(b1));
}

// D[m16-block wm][n32-block wn] += A_hi*B_hi + A_lo*B_hi + A_hi*B_lo over K=128
// A: [64 rows(m)][k] row-major; B: [128 rows(n)][k] row-major (TN layout, both non-trans)
__device__ __forceinline__ void gemm_dual(uint32_t aHi, uint32_t aLo,
                                          uint32_t bHi, uint32_t bLo,
                                          int wm, int wn, int lane, float d[4][4]) {
    const uint32_t lo16 = lane & 15;
    const uint32_t sel = (lane >> 4) * 16;           // +8 halfs for lanes 16-31
    const uint32_t aOff = (wm * 16 + lo16) * RB + sel;
    const uint32_t bOff = (wn * 32 + lo16) * RB + sel;
#pragma unroll
    for (int ks = 0; ks < 8; ++ks) {
        const uint32_t kb = ks * 32;                 // 16 halfs per k-step
        uint32_t ah[4], al[4], bh[8], bl[8];
        ldsm_x4(aHi + aOff + kb, ah);
        ldsm_x4(aLo + aOff + kb, al);
        ldsm_x4(bHi + bOff + kb, bh);
        ldsm_x4(bHi + bOff + 16 * RB + kb, bh + 4);
        ldsm_x4(bLo + bOff + kb, bl);
        ldsm_x4(bLo + bOff + 16 * RB + kb, bl + 4);
#pragma unroll
        for (int f = 0; f < 4; ++f) {
            const int base = (f >> 1) * 4, odd = f & 1;
            const uint32_t b0h = bh[base + odd], b1h = bh[base + odd + 2];
            const uint32_t b0l = bl[base + odd], b1l = bl[base + odd + 2];
            mma16816(d[f], ah, b0h, b1h);   // hi*hi
            mma16816(d[f], al, b0h, b1h);   // lo*hi
            mma16816(d[f], ah, b0l, b1l);   // hi*lo
        }
    }
}

__global__ __launch_bounds__(NTHR, 1)
void netvlad_mma(const float* __restrict__ x,
                 const float* __restrict__ conv_w,
                 const float* __restrict__ conv_b) {
    extern __shared__ unsigned char sm[];
    const uint32_t smb = smem_u32(sm);
    float* ls = (float*)(sm + XT_LO);   // overlays xT_lo after GEMM1

    __shared__ float bs_s[K], rn_s[TP], sinv_s[TP], red4[4][TP];

    const int n = blockIdx.x, tile = blockIdx.y;
    const int tid = threadIdx.x, lane = tid & 31, w = tid >> 5;
    const int wm = w & 3, wn = w >> 2;

    // ---- W fp32 -> fp16 hi/lo, [k][c] stride RB ----
    for (int idx = tid; idx < K * C / 2; idx += NTHR) {
        int k = idx >> 6, c2 = (idx & 63) * 2;
        float v0 = __ldg(conv_w + k * C + c2);
        float v1 = __ldg(conv_w + k * C + c2 + 1);
        __half h0 = __float2half_rn(v0), h1 = __float2half_rn(v1);
        __half l0 = __float2half_rn(v0 - __half2float(h0));
        __half l1 = __float2half_rn(v1 - __half2float(h1));
        *(__half2*)(sm + W_HI + k * RB + c2 * 2) = __halves2half2(h0, h1);
        *(__half2*)(sm + W_LO + k * RB + c2 * 2) = __halves2half2(l0, l1);
    }
    if (tid < K) bs_s[tid] = conv_b[tid];

    // ---- load x, split fp16 hi/lo, write x[c][p] and xT[p][c], ssq ----
    {
        const int p = tid & 127, q = tid >> 7;
        const float* xp = x + (size_t)n * C * HW + (size_t)tile * TP + p;
        float ss = 0.0f;
#pragma unroll
        for (int g = 0; g < 8; ++g) {
            int c = q * 32 + g * 4;
            float v0 = __ldg(xp + (size_t)(c + 0) * HW);
            float v1 = __ldg(xp + (size_t)(c + 1) * HW);
            float v2 = __ldg(xp + (size_t)(c + 2) * HW);
            float v3 = __ldg(xp + (size_t)(c + 3) * HW);
            ss += v0 * v0 + v1 * v1 + v2 * v2 + v3 * v3;
            __half h0 = __float2half_rn(v0), h1 = __float2half_rn(v1);
            __half h2 = __float2half_rn(v2), h3 = __float2half_rn(v3);
            __half l0 = __float2half_rn(v0 - __half2float(h0));
            __half l1 = __float2half_rn(v1 - __half2float(h1));
            __half l2 = __float2half_rn(v2 - __half2float(h2));
            __half l3 = __float2half_rn(v3 - __half2float(h3));
            unsigned a0 = (unsigned)__half_as_ushort(h0) | ((unsigned)__half_as_ushort(h1) << 16);
            unsigned a1 = (unsigned)__half_as_ushort(h2) | ((unsigned)__half_as_ushort(h3) << 16);
            unsigned b0 = (unsigned)__half_as_ushort(l0) | ((unsigned)__half_as_ushort(l1) << 16);
            unsigned b1 = (unsigned)__half_as_ushort(l2) | ((unsigned)__half_as_ushort(l3) << 16);
            *(ull*)(sm + XT_HI + p * RB + c * 2) = (ull)a0 | ((ull)a1 << 32);
            *(ull*)(sm + XT_LO + p * RB + c * 2) = (ull)b0 | ((ull)b1 << 32);
            *(__half*)(sm + X_HI + (c + 0) * RB + p * 2) = h0;
            *(__half*)(sm + X_HI + (c + 1) * RB + p * 2) = h1;
            *(__half*)(sm + X_HI + (c + 2) * RB + p * 2) = h2;
            *(__half*)(sm + X_HI + (c + 3) * RB + p * 2) = h3;
            *(__half*)(sm + X_LO + (c + 0) * RB + p * 2) = l0;
            *(__half*)(sm + X_LO + (c + 1) * RB + p * 2) = l1;
            *(__half*)(sm + X_LO + (c + 2) * RB + p * 2) = l2;
            *(__half*)(sm + X_LO + (c + 3) * RB + p * 2) = l3;
        }
        red4[q][p] = ss;
    }
    __syncthreads();
    if (tid < TP)
        rn_s[tid] = 1.0f / fmaxf(sqrtf(red4[0][tid] + red4[1][tid] + red4[2][tid] + red4[3][tid]), 1e-12f);
    __syncthreads();

    // ---- GEMM1: D1[k][p] = W @ xT^T (3 split passes) ----
    float d1[4][4];
#pragma unroll
    for (int f = 0; f < 4; ++f)
#pragma unroll
        for (int e = 0; e < 4; ++e) d1[f][e] = 0.0f;
    gemm_dual(smb + W_HI, smb + W_LO, smb + XT_HI, smb + XT_LO, wm, wn, lane, d1);
    __syncthreads();  // all warps done reading xT_lo before ls overlay writes

    // epilogue: ls[k][p] = dot*rn[p] + b[k]
    {
        const int k0 = wm * 16 + (lane >> 2);
        const float b0 = bs_s[k0], b1 = bs_s[k0 + 8];
#pragma unroll
        for (int f = 0; f < 4; ++f) {
            const int p = wn * 32 + f * 8 + 2 * (lane & 3);
            const float rn0 = rn_s[p], rn1 = rn_s[p + 1];
            ls[k0 * LS_STRIDE + p]           = d1[f][0] * rn0 + b0;
            ls[k0 * LS_STRIDE + p + 1]       = d1[f][1] * rn1 + b0;
            ls[(k0 + 8) * LS_STRIDE + p]     = d1[f][2] * rn0 + b1;
            ls[(k0 + 8) * LS_STRIDE + p + 1] = d1[f][3] * rn1 + b1;
        }
    }
    __syncthreads();

    // ---- softmax over k per pixel (4 k-quarters x 128 p) ----
    {
        const int p = tid & 127, q = tid >> 7;
        const int k0 = q * 16;
        float m = -1e30f;
#pragma unroll 8
        for (int i = 0; i < 16; ++i) m = fmaxf(m, ls[(k0 + i) * LS_STRIDE + p]);
        red4[q][p] = m;
        __syncthreads();
        float M = fmaxf(fmaxf(red4[0][p], red4[1][p]), fmaxf(red4[2][p], red4[3][p]));
        __syncthreads();
        float s = 0.0f;
#pragma unroll 8
        for (int i = 0; i < 16; ++i) {
            float e = __expf(ls[(k0 + i) * LS_STRIDE + p] - M);
            ls[(k0 + i) * LS_STRIDE + p] = e;
            s += e;
        }
        red4[q][p] = s;
        __syncthreads();
        if (tid < TP)
            sinv_s[tid] = 1.0f / (red4[0][tid] + red4[1][tid] + red4[2][tid] + red4[3][tid]);
        __syncthreads();
    }

    // ---- fold: asum partials + a' = e*sinv*rn as fp16 hi/lo [k][p] ----
    {
        const int kb = w * 4;
        float si[4], sir[4];
#pragma unroll
        for (int j = 0; j < 4; ++j) {
            int p = lane + 32 * j;
            si[j] = sinv_s[p];
            sir[j] = si[j] * rn_s[p];
        }
#pragma unroll
        for (int i = 0; i < 4; ++i) {
            const int k = kb + i;
            float sv = 0.0f;
#pragma unroll
            for (int j = 0; j < 4; ++j) {
                const int p = lane + 32 * j;
                float e = ls[k * LS_STRIDE + p];
                sv += e * si[j];
                float ap = e * sir[j];
                __half ah = __float2half_rn(ap);
                __half al = __float2half_rn(ap - __half2float(ah));
                *(__half*)(sm + A_HI + k * RB + p * 2) = ah;
                *(__half*)(sm + A_LO + k * RB + p * 2) = al;
            }
#pragma unroll
            for (int off = 16; off; off >>= 1) sv += __shfl_down_sync(0xffffffffu, sv, off);
            if (lane == 0) g_asum_part[(n * NTILES + tile) * K + k] = sv;
        }
    }
    __syncthreads();

    // ---- GEMM2: D2[k][c] = a' @ x^T (3 split passes) ----
    float d2[4][4];
#pragma unroll
    for (int f = 0; f < 4; ++f)
#pragma unroll
        for (int e = 0; e < 4; ++e) d2[f][e] = 0.0f;
    gemm_dual(smb + A_HI, smb + A_LO, smb + X_HI, smb + X_LO, wm, wn, lane, d2);

    // store partial [k][c] (unique slot, plain stores)
    {
        float* gp = g_part + (size_t)(n * NTILES + tile) * K * C;
        const int k0 = wm * 16 + (lane >> 2);
#pragma unroll
        for (int f = 0; f < 4; ++f) {
            const int c = wn * 32 + f * 8 + 2 * (lane & 3);
            *(float2*)(gp + k0 * C + c)       = make_float2(d2[f][0], d2[f][1]);
            *(float2*)(gp + (k0 + 8) * C + c) = make_float2(d2[f][2], d2[f][3]);
        }
    }
}

__global__ __launch_bounds__(256)
void reduce_part() {
    const int n = blockIdx.x;
    const int idx = blockIdx.y * 256 + threadIdx.x;   // 0..2047 float4 units (K*C/4)
    const float4* src = (const float4*)g_part + (size_t)n * NTILES * 2048 + idx;
    float4 acc = make_float4(0.f, 0.f, 0.f, 0.f);
#pragma unroll 8
    for (int t = 0; t < NTILES; ++t) {
        float4 v = src[(size_t)t * 2048];
        acc.x += v.x; acc.y += v.y; acc.z += v.z; acc.w += v.w;
    }
    ((float4*)g_vlad)[(size_t)n * 2048 + idx] = acc;
}

__global__ __launch_bounds__(256)
void netvlad_finalize(const float* __restrict__ centroids, float* __restrict__ out) {
    __shared__ float ys[KE * C];
    __shared__ float colss[8 * C];
    __shared__ float colinv[C];
    __shared__ float asl[KE];
    __shared__ float red[8];
    __shared__ float s_inv2;

    const int n = blockIdx.x, tid = threadIdx.x;

    if (tid < KE) {
        float s = 0.0f;
        const float* ap = g_asum_part + (size_t)n * NTILES * K + tid;
#pragma unroll 8
        for (int t = 0; t < NTILES; ++t) s += ap[t * K];
        asl[tid] = s;
    }
    __syncthreads();

    const int cg = (tid & 31) * 4;
    float4 ss4 = make_float4(0.f, 0.f, 0.f, 0.f);
#pragma unroll
    for (int r = 0; r < 7; ++r) {
        int e4 = tid + r * 256;            // 0..1791 -> k<56
        int k = e4 >> 5;
        float a = asl[k];
        float4 s = ((const float4*)g_vlad)[(size_t)n * 2048 + k * 32 + (e4 & 31)];
        float4 ce = *(const float4*)(centroids + k * C + cg);
        float4 y;
        y.x = s.x - a * ce.x; y.y = s.y - a * ce.y;
        y.z = s.z - a * ce.z; y.w = s.w - a * ce.w;
        *(float4*)(ys + k * C + cg) = y;
        ss4.x += y.x * y.x; ss4.y += y.y * y.y;
        ss4.z += y.z * y.z; ss4.w += y.w * y.w;
    }
    *(float4*)(colss + (tid >> 5) * C + cg) = ss4;
    __syncthreads();

    float gs = 0.0f;
    if (tid < C) {
        float cs = 0.0f;
#pragma unroll
        for (int g = 0; g < 8; ++g) cs += colss[g * C + tid];
        float i1 = 1.0f / fmaxf(sqrtf(cs), 1e-12f);
        gs = cs * i1 * i1;
        colinv[tid] = i1;
    }
    __syncthreads();
#pragma unroll
    for (int off = 16; off; off >>= 1) gs += __shfl_down_sync(0xffffffffu, gs, off);
    if ((tid & 31) == 0) red[tid >> 5] = gs;
    __syncthreads();
    if (tid == 0) {
        float t = red[0] + red[1] + red[2] + red[3];
        s_inv2 = 1.0f / fmaxf(sqrtf(t), 1e-12f);
    }
    __syncthreads();
    const float inv2 = s_inv2;
    float* op = out + (size_t)n * KE * C;
    for (int idx = tid; idx < KE * C; idx += 256)
        op[idx] = ys[idx] * colinv[idx & 127] * inv2;
}

extern "C" void kernel_launch(void* const* d_in, const int* in_sizes, int n_in,
                              void* d_out, int out_size) {
    const float* x      = (const float*)d_in[0];
    const float* conv_w = (const float*)d_in[1];
    const float* conv_b = (const float*)d_in[2];
    const float* cen    = (const float*)d_in[3];
    float* out = (float*)d_out;

    cudaFuncSetAttribute(netvlad_mma, cudaFuncAttributeMaxDynamicSharedMemorySize, SMEM_DYN);

    netvlad_mma<<<dim3(NB, NTILES), NTHR, SMEM_DYN>>>(x, conv_w, conv_b);
    reduce_part<<<dim3(NB, 8), 256>>>();
    netvlad_finalize<<<NB, 256>>>(cen, out);
}

// round 8
// speedup vs baseline: 2.0455x; 1.1385x over previous
#include <cuda_runtime.h>
#include <cuda_fp16.h>
#include <math.h>
#include <stdint.h>

typedef unsigned long long ull;

#define NB 32
#define C 128
#define HW 4096
#define K 64
#define KE 56
#define TP 128
#define NTILES 32
#define NTHR 512

#define RB 272            // row bytes (136 halfs); 4-bank shift per row, ldmatrix conflict-free

// dynamic smem byte offsets
#define XT_HI 0           // xT[p][c] hi  128*272 = 34816
#define XT_LO 34816       // xT[p][c] lo
#define W_HI  69632       // W[k][c] hi    64*272 = 17408
#define W_LO  87040
#define A_HI  104448      // a'[k][p] hi
#define A_LO  121856
#define SMEM_DYN 139264

__device__ float g_part[NB * NTILES * K * C];
__device__ float g_asum_part[NB * NTILES * K];
__device__ float g_vlad[NB * K * C];

__device__ __forceinline__ uint32_t smem_u32(const void* p) {
    uint32_t a;
    asm("{ .reg .u64 t; cvta.to.shared.u64 t, %1; cvt.u32.u64 %0, t; }" : "=r"(a) : "l"(p));
    return a;
}
__device__ __forceinline__ void ldsm_x4(uint32_t a, uint32_t* r) {
    asm volatile("ldmatrix.sync.aligned.m8n8.x4.shared.b16 {%0,%1,%2,%3}, [%4];"
                 : "=r"(r[0]), "=r"(r[1]), "=r"(r[2]), "=r"(r[3]) : "r"(a));
}
__device__ __forceinline__ void ldsm_x4t(uint32_t a, uint32_t* r) {
    asm volatile("ldmatrix.sync.aligned.m8n8.x4.trans.shared.b16 {%0,%1,%2,%3}, [%4];"
                 : "=r"(r[0]), "=r"(r[1]), "=r"(r[2]), "=r"(r[3]) : "r"(a));
}
__device__ __forceinline__ void mma16816(float* d, const uint32_t* a, uint32_t b0, uint32_t b1) {
    asm volatile("mma.sync.aligned.m16n8k16.row.col.f32.f16.f16.f32 "
                 "{%0,%1,%2,%3}, {%4,%5,%6,%7}, {%8,%9}, {%0,%1,%2,%3};"
                 : "+f"(d[0]), "+f"(d[1]), "+f"(d[2]), "+f"(d[3])
                 : "r"(a[0]), "r"(a[1]), "r"(a[2]), "r"(a[3]), "r"(b0), "r"(b1));
}

// GEMM1: A[64(m)][k] row-major, B[128(n)][k] row-major -> both non-trans ldmatrix
__device__ __forceinline__ void gemm_nn(uint32_t aHi, uint32_t aLo,
                                        uint32_t bHi, uint32_t bLo,
                                        int wm, int wn, int lane, float d[4][4]) {
    const uint32_t lo16 = lane & 15;
    const uint32_t sel = (lane >> 4) * 16;
    const uint32_t aOff = (wm * 16 + lo16) * RB + sel;
    const uint32_t bOff = (wn * 32 + lo16) * RB + sel;
#pragma unroll
    for (int ks = 0; ks < 8; ++ks) {
        const uint32_t kb = ks * 32;
        uint32_t ah[4], al[4], bh[8], bl[8];
        ldsm_x4(aHi + aOff + kb, ah);
        ldsm_x4(aLo + aOff + kb, al);
        ldsm_x4(bHi + bOff + kb, bh);
        ldsm_x4(bHi + bOff + 16 * RB + kb, bh + 4);
        ldsm_x4(bLo + bOff + kb, bl);
        ldsm_x4(bLo + bOff + 16 * RB + kb, bl + 4);
#pragma unroll
        for (int f = 0; f < 4; ++f) {
            const int base = (f >> 1) * 4, odd = f & 1;
            mma16816(d[f], ah, bh[base + odd], bh[base + odd + 2]);
            mma16816(d[f], al, bh[base + odd], bh[base + odd + 2]);
            mma16816(d[f], ah, bl[base + odd], bl[base + odd + 2]);
        }
    }
}

// GEMM2: A[64(m)][k=p] row-major non-trans; B from xT[p][c] = [k][n] storage via trans ldmatrix
__device__ __forceinline__ void gemm_nt(uint32_t aHi, uint32_t aLo,
                                        uint32_t bHi, uint32_t bLo,
                                        int wm, int wn, int lane, float d[4][4]) {
    const uint32_t lo16 = lane & 15;
    const uint32_t sel = (lane >> 4) * 16;
    const uint32_t aOff = (wm * 16 + lo16) * RB + sel;
    // trans-B lane address: row = p0 + (lane&7) + (lane>=16)*8 ; col = n0 + ((lane>>3)&1)*8 halfs
    const uint32_t brow = (lane & 7) + ((lane >> 4) << 3);
    const uint32_t bOff = brow * RB + (wn * 32 + ((lane >> 3) & 1) * 8) * 2;
#pragma unroll
    for (int ks = 0; ks < 8; ++ks) {
        const uint32_t kb = ks * 32;        // A: 16 halfs of p per step
        const uint32_t bb = ks * 16 * RB;   // B: 16 p-rows per step
        uint32_t ah[4], al[4], bh[8], bl[8];
        ldsm_x4(aHi + aOff + kb, ah);
        ldsm_x4(aLo + aOff + kb, al);
        ldsm_x4t(bHi + bOff + bb, bh);
        ldsm_x4t(bHi + bOff + bb + 32, bh + 4);   // n +16 cols = +32 bytes
        ldsm_x4t(bLo + bOff + bb, bl);
        ldsm_x4t(bLo + bOff + bb + 32, bl + 4);
#pragma unroll
        for (int f = 0; f < 4; ++f) {
            const int base = (f >> 1) * 4, odd = f & 1;
            mma16816(d[f], ah, bh[base + odd], bh[base + odd + 2]);
            mma16816(d[f], al, bh[base + odd], bh[base + odd + 2]);
            mma16816(d[f], ah, bl[base + odd], bl[base + odd + 2]);
        }
    }
}

__global__ __launch_bounds__(NTHR, 1)
void netvlad_mma(const float* __restrict__ x,
                 const float* __restrict__ conv_w,
                 const float* __restrict__ conv_b) {
    extern __shared__ unsigned char sm[];
    const uint32_t smb = smem_u32(sm);

    __shared__ float bs_s[K], rn_s[TP], ms_s[TP], sinv_s[TP];
    __shared__ float red4[4][TP];
    __shared__ float asw[16][16];

    const int n = blockIdx.x, tile = blockIdx.y;
    const int tid = threadIdx.x, lane = tid & 31, w = tid >> 5;
    const int wm = w & 3, wn = w >> 2;

    // ---- W fp32 -> fp16 hi/lo [k][c], stride RB ----
    for (int idx = tid; idx < K * C / 2; idx += NTHR) {
        int k = idx >> 6, c2 = (idx & 63) * 2;
        float v0 = __ldg(conv_w + k * C + c2);
        float v1 = __ldg(conv_w + k * C + c2 + 1);
        __half h0 = __float2half_rn(v0), h1 = __float2half_rn(v1);
        __half l0 = __float2half_rn(v0 - __half2float(h0));
        __half l1 = __float2half_rn(v1 - __half2float(h1));
        *(__half2*)(sm + W_HI + k * RB + c2 * 2) = __halves2half2(h0, h1);
        *(__half2*)(sm + W_LO + k * RB + c2 * 2) = __halves2half2(l0, l1);
    }
    if (tid < K) bs_s[tid] = conv_b[tid];

    // ---- load x, split fp16 hi/lo into xT[p][c], ssq ----
    {
        const int p = tid & 127, q = tid >> 7;
        const float* xp = x + (size_t)n * C * HW + (size_t)tile * TP + p;
        float ss = 0.0f;
#pragma unroll
        for (int g = 0; g < 8; ++g) {
            int c = q * 32 + g * 4;
            float v0 = __ldg(xp + (size_t)(c + 0) * HW);
            float v1 = __ldg(xp + (size_t)(c + 1) * HW);
            float v2 = __ldg(xp + (size_t)(c + 2) * HW);
            float v3 = __ldg(xp + (size_t)(c + 3) * HW);
            ss += v0 * v0 + v1 * v1 + v2 * v2 + v3 * v3;
            __half h0 = __float2half_rn(v0), h1 = __float2half_rn(v1);
            __half h2 = __float2half_rn(v2), h3 = __float2half_rn(v3);
            __half l0 = __float2half_rn(v0 - __half2float(h0));
            __half l1 = __float2half_rn(v1 - __half2float(h1));
            __half l2 = __float2half_rn(v2 - __half2float(h2));
            __half l3 = __float2half_rn(v3 - __half2float(h3));
            unsigned a0 = (unsigned)__half_as_ushort(h0) | ((unsigned)__half_as_ushort(h1) << 16);
            unsigned a1 = (unsigned)__half_as_ushort(h2) | ((unsigned)__half_as_ushort(h3) << 16);
            unsigned b0 = (unsigned)__half_as_ushort(l0) | ((unsigned)__half_as_ushort(l1) << 16);
            unsigned b1 = (unsigned)__half_as_ushort(l2) | ((unsigned)__half_as_ushort(l3) << 16);
            *(ull*)(sm + XT_HI + p * RB + c * 2) = (ull)a0 | ((ull)a1 << 32);
            *(ull*)(sm + XT_LO + p * RB + c * 2) = (ull)b0 | ((ull)b1 << 32);
        }
        red4[q + (q & 2)][p] = 0.0f;   // no-op placeholder avoidance (keep simple)
        red4[q][p] = ss;
    }
    __syncthreads();
    if (tid < TP) {
        float tot = red4[0][tid] + red4[1][tid] + red4[2][tid] + red4[3][tid];
        rn_s[tid] = 1.0f / fmaxf(sqrtf(tot), 1e-12f);
    }
    __syncthreads();

    // ---- GEMM1: D1[k][p] ----
    float d1[4][4];
#pragma unroll
    for (int f = 0; f < 4; ++f)
#pragma unroll
        for (int e = 0; e < 4; ++e) d1[f][e] = 0.0f;
    gemm_nn(smb + W_HI, smb + W_LO, smb + XT_HI, smb + XT_LO, wm, wn, lane, d1);

    // ---- logits in registers; softmax via shfl + tiny smem ----
    const int k0 = wm * 16 + (lane >> 2);
    const float bk0 = bs_s[k0], bk1 = bs_s[k0 + 8];
    float rnv[4][2];
    float mx[4][2];
#pragma unroll
    for (int f = 0; f < 4; ++f) {
        const int p = wn * 32 + f * 8 + 2 * (lane & 3);
        const float r0 = rn_s[p], r1 = rn_s[p + 1];
        rnv[f][0] = r0; rnv[f][1] = r1;
        d1[f][0] = d1[f][0] * r0 + bk0;
        d1[f][1] = d1[f][1] * r1 + bk0;
        d1[f][2] = d1[f][2] * r0 + bk1;
        d1[f][3] = d1[f][3] * r1 + bk1;
        mx[f][0] = fmaxf(d1[f][0], d1[f][2]);
        mx[f][1] = fmaxf(d1[f][1], d1[f][3]);
    }
#pragma unroll
    for (int off = 4; off <= 16; off <<= 1)
#pragma unroll
        for (int f = 0; f < 4; ++f) {
            mx[f][0] = fmaxf(mx[f][0], __shfl_xor_sync(0xffffffffu, mx[f][0], off));
            mx[f][1] = fmaxf(mx[f][1], __shfl_xor_sync(0xffffffffu, mx[f][1], off));
        }
    if ((lane >> 2) == 0) {
#pragma unroll
        for (int f = 0; f < 4; ++f) {
            const int p = wn * 32 + f * 8 + 2 * lane;
            red4[wm][p] = mx[f][0];
            red4[wm][p + 1] = mx[f][1];
        }
    }
    __syncthreads();
    if (tid < TP)
        ms_s[tid] = fmaxf(fmaxf(red4[0][tid], red4[1][tid]), fmaxf(red4[2][tid], red4[3][tid]));
    __syncthreads();

    float sme[4][2];
#pragma unroll
    for (int f = 0; f < 4; ++f) {
        const int p = wn * 32 + f * 8 + 2 * (lane & 3);
        const float M0 = ms_s[p], M1 = ms_s[p + 1];
        d1[f][0] = __expf(d1[f][0] - M0);
        d1[f][1] = __expf(d1[f][1] - M1);
        d1[f][2] = __expf(d1[f][2] - M0);
        d1[f][3] = __expf(d1[f][3] - M1);
        sme[f][0] = d1[f][0] + d1[f][2];
        sme[f][1] = d1[f][1] + d1[f][3];
    }
#pragma unroll
    for (int off = 4; off <= 16; off <<= 1)
#pragma unroll
        for (int f = 0; f < 4; ++f) {
            sme[f][0] += __shfl_xor_sync(0xffffffffu, sme[f][0], off);
            sme[f][1] += __shfl_xor_sync(0xffffffffu, sme[f][1], off);
        }
    if ((lane >> 2) == 0) {
#pragma unroll
        for (int f = 0; f < 4; ++f) {
            const int p = wn * 32 + f * 8 + 2 * lane;
            red4[wm][p] = sme[f][0];
            red4[wm][p + 1] = sme[f][1];
        }
    }
    __syncthreads();
    if (tid < TP)
        sinv_s[tid] = 1.0f / (red4[0][tid] + red4[1][tid] + red4[2][tid] + red4[3][tid]);
    __syncthreads();

    // ---- a = e*sinv; asum partials; a' = a*rn split to smem as half2 ----
    float ak0 = 0.0f, ak1 = 0.0f;
#pragma unroll
    for (int f = 0; f < 4; ++f) {
        const int p = wn * 32 + f * 8 + 2 * (lane & 3);
        const float s0 = sinv_s[p], s1 = sinv_s[p + 1];
        const float a00 = d1[f][0] * s0, a01 = d1[f][1] * s1;
        const float a10 = d1[f][2] * s0, a11 = d1[f][3] * s1;
        ak0 += a00 + a01;
        ak1 += a10 + a11;
        const float q00 = a00 * rnv[f][0], q01 = a01 * rnv[f][1];
        const float q10 = a10 * rnv[f][0], q11 = a11 * rnv[f][1];
        __half h00 = __float2half_rn(q00), h01 = __float2half_rn(q01);
        __half h10 = __float2half_rn(q10), h11 = __float2half_rn(q11);
        *(__half2*)(sm + A_HI + k0 * RB + p * 2) = __halves2half2(h00, h01);
        *(__half2*)(sm + A_HI + (k0 + 8) * RB + p * 2) = __halves2half2(h10, h11);
        *(__half2*)(sm + A_LO + k0 * RB + p * 2) =
            __halves2half2(__float2half_rn(q00 - __half2float(h00)),
                           __float2half_rn(q01 - __half2float(h01)));
        *(__half2*)(sm + A_LO + (k0 + 8) * RB + p * 2) =
            __halves2half2(__float2half_rn(q10 - __half2float(h10)),
                           __float2half_rn(q11 - __half2float(h11)));
    }
    ak0 += __shfl_xor_sync(0xffffffffu, ak0, 1);
    ak0 += __shfl_xor_sync(0xffffffffu, ak0, 2);
    ak1 += __shfl_xor_sync(0xffffffffu, ak1, 1);
    ak1 += __shfl_xor_sync(0xffffffffu, ak1, 2);
    if ((lane & 3) == 0) {
        asw[w][lane >> 2] = ak0;
        asw[w][8 + (lane >> 2)] = ak1;
    }
    __syncthreads();
    if (tid < K) {
        const int wmk = tid >> 4, kk = tid & 15;
        g_asum_part[(n * NTILES + tile) * K + tid] =
            asw[wmk][kk] + asw[4 + wmk][kk] + asw[8 + wmk][kk] + asw[12 + wmk][kk];
    }

    // ---- GEMM2: D2[k][c] = a'[k][p] @ xT[p][c] (trans-B) ----
    float d2[4][4];
#pragma unroll
    for (int f = 0; f < 4; ++f)
#pragma unroll
        for (int e = 0; e < 4; ++e) d2[f][e] = 0.0f;
    __syncthreads();   // A' visible to all warps
    gemm_nt(smb + A_HI, smb + A_LO, smb + XT_HI, smb + XT_LO, wm, wn, lane, d2);

    // store partial [k][c]
    {
        float* gp = g_part + (size_t)(n * NTILES + tile) * K * C;
#pragma unroll
        for (int f = 0; f < 4; ++f) {
            const int c = wn * 32 + f * 8 + 2 * (lane & 3);
            *(float2*)(gp + k0 * C + c)       = make_float2(d2[f][0], d2[f][1]);
            *(float2*)(gp + (k0 + 8) * C + c) = make_float2(d2[f][2], d2[f][3]);
        }
    }
}

__global__ __launch_bounds__(256)
void reduce_part() {
    const int n = blockIdx.x;
    const int idx = blockIdx.y * 256 + threadIdx.x;
    const float4* src = (const float4*)g_part + (size_t)n * NTILES * 2048 + idx;
    float4 acc = make_float4(0.f, 0.f, 0.f, 0.f);
#pragma unroll 8
    for (int t = 0; t < NTILES; ++t) {
        float4 v = src[(size_t)t * 2048];
        acc.x += v.x; acc.y += v.y; acc.z += v.z; acc.w += v.w;
    }
    ((float4*)g_vlad)[(size_t)n * 2048 + idx] = acc;
}

__global__ __launch_bounds__(256)
void netvlad_finalize(const float* __restrict__ centroids, float* __restrict__ out) {
    __shared__ float ys[KE * C];
    __shared__ float colss[8 * C];
    __shared__ float colinv[C];
    __shared__ float asl[KE];
    __shared__ float red[8];
    __shared__ float s_inv2;

    const int n = blockIdx.x, tid = threadIdx.x;

    if (tid < KE) {
        float s = 0.0f;
        const float* ap = g_asum_part + (size_t)n * NTILES * K + tid;
#pragma unroll 8
        for (int t = 0; t < NTILES; ++t) s += ap[t * K];
        asl[tid] = s;
    }
    __syncthreads();

    const int cg = (tid & 31) * 4;
    float4 ss4 = make_float4(0.f, 0.f, 0.f, 0.f);
#pragma unroll
    for (int r = 0; r < 7; ++r) {
        int e4 = tid + r * 256;
        int k = e4 >> 5;
        float a = asl[k];
        float4 s = ((const float4*)g_vlad)[(size_t)n * 2048 + k * 32 + (e4 & 31)];
        float4 ce = *(const float4*)(centroids + k * C + cg);
        float4 y;
        y.x = s.x - a * ce.x; y.y = s.y - a * ce.y;
        y.z = s.z - a * ce.z; y.w = s.w - a * ce.w;
        *(float4*)(ys + k * C + cg) = y;
        ss4.x += y.x * y.x; ss4.y += y.y * y.y;
        ss4.z += y.z * y.z; ss4.w += y.w * y.w;
    }
    *(float4*)(colss + (tid >> 5) * C + cg) = ss4;
    __syncthreads();

    float gs = 0.0f;
    if (tid < C) {
        float cs = 0.0f;
#pragma unroll
        for (int g = 0; g < 8; ++g) cs += colss[g * C + tid];
        float i1 = 1.0f / fmaxf(sqrtf(cs), 1e-12f);
        gs = cs * i1 * i1;
        colinv[tid] = i1;
    }
    __syncthreads();
#pragma unroll
    for (int off = 16; off; off >>= 1) gs += __shfl_down_sync(0xffffffffu, gs, off);
    if ((tid & 31) == 0) red[tid >> 5] = gs;
    __syncthreads();
    if (tid == 0) {
        float t = red[0] + red[1] + red[2] + red[3];
        s_inv2 = 1.0f / fmaxf(sqrtf(t), 1e-12f);
    }
    __syncthreads();
    const float inv2 = s_inv2;
    float* op = out + (size_t)n * KE * C;
    for (int idx = tid; idx < KE * C; idx += 256)
        op[idx] = ys[idx] * colinv[idx & 127] * inv2;
}

extern "C" void kernel_launch(void* const* d_in, const int* in_sizes, int n_in,
                              void* d_out, int out_size) {
    const float* x      = (const float*)d_in[0];
    const float* conv_w = (const float*)d_in[1];
    const float* conv_b = (const float*)d_in[2];
    const float* cen    = (const float*)d_in[3];
    float* out = (float*)d_out;

    cudaFuncSetAttribute(netvlad_mma, cudaFuncAttributeMaxDynamicSharedMemorySize, SMEM_DYN);

    netvlad_mma<<<dim3(NB, NTILES), NTHR, SMEM_DYN>>>(x, conv_w, conv_b);
    reduce_part<<<dim3(NB, 8), 256>>>();
    netvlad_finalize<<<NB, 256>>>(cen, out);
}

// round 9
// speedup vs baseline: 2.1976x; 1.0744x over previous
#include <cuda_runtime.h>
#include <cuda_fp16.h>
#include <math.h>
#include <stdint.h>

typedef unsigned long long ull;

#define NB 32
#define C 128
#define HW 4096
#define K 64
#define KE 56
#define TP 128
#define NTILES 32
#define NTHR 256

#define RB 272            // row bytes (136 halfs); 4-bank shift per row, ldmatrix conflict-free

// dynamic smem byte offsets; a' overlays W (W dead after GEMM1)
#define XT_HI 0           // xT[p][c] hi  128*272 = 34816
#define XT_LO 34816       // xT[p][c] lo
#define W_HI  69632       // W[k][c] hi -> a'[k][p] hi after GEMM1
#define W_LO  87040       // W[k][c] lo -> a'[k][p] lo
#define SMEM_DYN 104448   // 102 KB -> 2 CTAs/SM

__device__ float g_part[NB * NTILES * K * C];
__device__ float g_asum_part[NB * NTILES * K];
__device__ float g_vlad[NB * K * C];

__device__ __forceinline__ uint32_t smem_u32(const void* p) {
    uint32_t a;
    asm("{ .reg .u64 t; cvta.to.shared.u64 t, %1; cvt.u32.u64 %0, t; }" : "=r"(a) : "l"(p));
    return a;
}
__device__ __forceinline__ void ldsm_x4(uint32_t a, uint32_t* r) {
    asm volatile("ldmatrix.sync.aligned.m8n8.x4.shared.b16 {%0,%1,%2,%3}, [%4];"
                 : "=r"(r[0]), "=r"(r[1]), "=r"(r[2]), "=r"(r[3]) : "r"(a));
}
__device__ __forceinline__ void ldsm_x4t(uint32_t a, uint32_t* r) {
    asm volatile("ldmatrix.sync.aligned.m8n8.x4.trans.shared.b16 {%0,%1,%2,%3}, [%4];"
                 : "=r"(r[0]), "=r"(r[1]), "=r"(r[2]), "=r"(r[3]) : "r"(a));
}
__device__ __forceinline__ void mma16816(float* d, const uint32_t* a, uint32_t b0, uint32_t b1) {
    asm volatile("mma.sync.aligned.m16n8k16.row.col.f32.f16.f16.f32 "
                 "{%0,%1,%2,%3}, {%4,%5,%6,%7}, {%8,%9}, {%0,%1,%2,%3};"
                 : "+f"(d[0]), "+f"(d[1]), "+f"(d[2]), "+f"(d[3])
                 : "r"(a[0]), "r"(a[1]), "r"(a[2]), "r"(a[3]), "r"(b0), "r"(b1));
}

// GEMM1: A = W[k][c] (m16), B = xT[p][c] (n64), both row-major [rows][k] -> non-trans
__device__ __forceinline__ void gemm_nn(const uint32_t smb, int wm, int wn, int lane,
                                        float d[8][4]) {
    const uint32_t lo16 = lane & 15;
    const uint32_t sel = (lane >> 4) * 16;
    const uint32_t aOff = (wm * 16 + lo16) * RB + sel;
    const uint32_t bOff = (wn * 64 + lo16) * RB + sel;
#pragma unroll
    for (int ks = 0; ks < 8; ++ks) {
        const uint32_t kb = ks * 32;
        uint32_t ah[4], al[4], bh[16], bl[16];
        ldsm_x4(smb + W_HI + aOff + kb, ah);
        ldsm_x4(smb + W_LO + aOff + kb, al);
#pragma unroll
        for (int t = 0; t < 4; ++t) {
            ldsm_x4(smb + XT_HI + bOff + t * 16 * RB + kb, bh + t * 4);
            ldsm_x4(smb + XT_LO + bOff + t * 16 * RB + kb, bl + t * 4);
        }
#pragma unroll
        for (int f = 0; f < 8; ++f) {
            const int t = f >> 1, odd = f & 1;
            mma16816(d[f], ah, bh[t * 4 + odd], bh[t * 4 + odd + 2]);
            mma16816(d[f], al, bh[t * 4 + odd], bh[t * 4 + odd + 2]);
            mma16816(d[f], ah, bl[t * 4 + odd], bl[t * 4 + odd + 2]);
        }
    }
}

// GEMM2: A = a'[k][p] (m16, non-trans); B from xT[p][c] storage via trans ldmatrix (n64)
__device__ __forceinline__ void gemm_nt(const uint32_t smb, int wm, int wn, int lane,
                                        float d[8][4]) {
    const uint32_t lo16 = lane & 15;
    const uint32_t sel = (lane >> 4) * 16;
    const uint32_t aOff = (wm * 16 + lo16) * RB + sel;
    const uint32_t brow = (lane & 7) + ((lane >> 4) << 3);
    const uint32_t bOff = brow * RB + (wn * 64 + ((lane >> 3) & 1) * 8) * 2;
#pragma unroll
    for (int ks = 0; ks < 8; ++ks) {
        const uint32_t kb = ks * 32;        // A: 16 p-halfs per step
        const uint32_t bb = ks * 16 * RB;   // B: 16 p-rows per step
        uint32_t ah[4], al[4], bh[16], bl[16];
        ldsm_x4(smb + W_HI + aOff + kb, ah);   // a' hi (overlaid)
        ldsm_x4(smb + W_LO + aOff + kb, al);   // a' lo
#pragma unroll
        for (int t = 0; t < 4; ++t) {
            ldsm_x4t(smb + XT_HI + bOff + bb + t * 32, bh + t * 4);
            ldsm_x4t(smb + XT_LO + bOff + bb + t * 32, bl + t * 4);
        }
#pragma unroll
        for (int f = 0; f < 8; ++f) {
            const int t = f >> 1, odd = f & 1;
            mma16816(d[f], ah, bh[t * 4 + odd], bh[t * 4 + odd + 2]);
            mma16816(d[f], al, bh[t * 4 + odd], bh[t * 4 + odd + 2]);
            mma16816(d[f], ah, bl[t * 4 + odd], bl[t * 4 + odd + 2]);
        }
    }
}

__global__ __launch_bounds__(NTHR, 2)
void netvlad_mma(const float* __restrict__ x,
                 const float* __restrict__ conv_w,
                 const float* __restrict__ conv_b) {
    extern __shared__ unsigned char sm[];
    const uint32_t smb = smem_u32(sm);

    __shared__ float bs_s[K], rn_s[TP], ms_s[TP], sinv_s[TP];
    __shared__ float red4[4][TP];
    __shared__ float asw[8][16];

    const int n = blockIdx.x, tile = blockIdx.y;
    const int tid = threadIdx.x, lane = tid & 31, w = tid >> 5;
    const int wm = w & 3, wn = w >> 2;   // 4 m-tiles x 2 n-halves

    // ---- W fp32 -> fp16 hi/lo [k][c], stride RB ----
    for (int idx = tid; idx < K * C / 2; idx += NTHR) {
        int k = idx >> 6, c2 = (idx & 63) * 2;
        float v0 = __ldg(conv_w + k * C + c2);
        float v1 = __ldg(conv_w + k * C + c2 + 1);
        __half h0 = __float2half_rn(v0), h1 = __float2half_rn(v1);
        __half l0 = __float2half_rn(v0 - __half2float(h0));
        __half l1 = __float2half_rn(v1 - __half2float(h1));
        *(__half2*)(sm + W_HI + k * RB + c2 * 2) = __halves2half2(h0, h1);
        *(__half2*)(sm + W_LO + k * RB + c2 * 2) = __halves2half2(l0, l1);
    }
    if (tid < K) bs_s[tid] = conv_b[tid];

    // ---- load x, split fp16 hi/lo into xT[p][c], ssq ----
    {
        const int p = tid & 127, q = tid >> 7;   // q in {0,1}, 64 c each
        const float* xp = x + (size_t)n * C * HW + (size_t)tile * TP + p;
        float ss = 0.0f;
#pragma unroll
        for (int g = 0; g < 16; ++g) {
            int c = q * 64 + g * 4;
            float v0 = __ldg(xp + (size_t)(c + 0) * HW);
            float v1 = __ldg(xp + (size_t)(c + 1) * HW);
            float v2 = __ldg(xp + (size_t)(c + 2) * HW);
            float v3 = __ldg(xp + (size_t)(c + 3) * HW);
            ss += v0 * v0 + v1 * v1 + v2 * v2 + v3 * v3;
            __half h0 = __float2half_rn(v0), h1 = __float2half_rn(v1);
            __half h2 = __float2half_rn(v2), h3 = __float2half_rn(v3);
            __half l0 = __float2half_rn(v0 - __half2float(h0));
            __half l1 = __float2half_rn(v1 - __half2float(h1));
            __half l2 = __float2half_rn(v2 - __half2float(h2));
            __half l3 = __float2half_rn(v3 - __half2float(h3));
            unsigned a0 = (unsigned)__half_as_ushort(h0) | ((unsigned)__half_as_ushort(h1) << 16);
            unsigned a1 = (unsigned)__half_as_ushort(h2) | ((unsigned)__half_as_ushort(h3) << 16);
            unsigned b0 = (unsigned)__half_as_ushort(l0) | ((unsigned)__half_as_ushort(l1) << 16);
            unsigned b1 = (unsigned)__half_as_ushort(l2) | ((unsigned)__half_as_ushort(l3) << 16);
            *(ull*)(sm + XT_HI + p * RB + c * 2) = (ull)a0 | ((ull)a1 << 32);
            *(ull*)(sm + XT_LO + p * RB + c * 2) = (ull)b0 | ((ull)b1 << 32);
        }
        red4[q][p] = ss;
    }
    __syncthreads();
    if (tid < TP)
        rn_s[tid] = 1.0f / fmaxf(sqrtf(red4[0][tid] + red4[1][tid]), 1e-12f);
    __syncthreads();

    // ---- GEMM1: D1[k][p], warp = m16 x n64 ----
    float d1[8][4];
#pragma unroll
    for (int f = 0; f < 8; ++f)
#pragma unroll
        for (int e = 0; e < 4; ++e) d1[f][e] = 0.0f;
    gemm_nn(smb, wm, wn, lane, d1);

    // ---- logits in registers; softmax via shfl + tiny smem ----
    const int k0 = wm * 16 + (lane >> 2);
    const float bk0 = bs_s[k0], bk1 = bs_s[k0 + 8];
#pragma unroll
    for (int f = 0; f < 8; ++f) {
        const int p = wn * 64 + f * 8 + 2 * (lane & 3);
        const float r0 = rn_s[p], r1 = rn_s[p + 1];
        d1[f][0] = d1[f][0] * r0 + bk0;
        d1[f][1] = d1[f][1] * r1 + bk0;
        d1[f][2] = d1[f][2] * r0 + bk1;
        d1[f][3] = d1[f][3] * r1 + bk1;
    }
    // per-pixel max over this warp's 16 k (shfl over m-lane groups)
#pragma unroll
    for (int f = 0; f < 8; ++f) {
        float m0 = fmaxf(d1[f][0], d1[f][2]);
        float m1 = fmaxf(d1[f][1], d1[f][3]);
#pragma unroll
        for (int off = 4; off <= 16; off <<= 1) {
            m0 = fmaxf(m0, __shfl_xor_sync(0xffffffffu, m0, off));
            m1 = fmaxf(m1, __shfl_xor_sync(0xffffffffu, m1, off));
        }
        if ((lane >> 2) == 0) {
            const int p = wn * 64 + f * 8 + 2 * lane;
            red4[wm][p] = m0;
            red4[wm][p + 1] = m1;
        }
    }
    __syncthreads();
    if (tid < TP)
        ms_s[tid] = fmaxf(fmaxf(red4[0][tid], red4[1][tid]), fmaxf(red4[2][tid], red4[3][tid]));
    __syncthreads();

#pragma unroll
    for (int f = 0; f < 8; ++f) {
        const int p = wn * 64 + f * 8 + 2 * (lane & 3);
        const float M0 = ms_s[p], M1 = ms_s[p + 1];
        d1[f][0] = __expf(d1[f][0] - M0);
        d1[f][1] = __expf(d1[f][1] - M1);
        d1[f][2] = __expf(d1[f][2] - M0);
        d1[f][3] = __expf(d1[f][3] - M1);
        float s0 = d1[f][0] + d1[f][2];
        float s1 = d1[f][1] + d1[f][3];
#pragma unroll
        for (int off = 4; off <= 16; off <<= 1) {
            s0 += __shfl_xor_sync(0xffffffffu, s0, off);
            s1 += __shfl_xor_sync(0xffffffffu, s1, off);
        }
        if ((lane >> 2) == 0) {
            const int p2 = wn * 64 + f * 8 + 2 * lane;
            red4[wm][p2] = s0;
            red4[wm][p2 + 1] = s1;
        }
    }
    __syncthreads();
    if (tid < TP)
        sinv_s[tid] = 1.0f / (red4[0][tid] + red4[1][tid] + red4[2][tid] + red4[3][tid]);
    __syncthreads();   // also: every warp past GEMM1 -> W buffers now dead, safe to overlay

    // ---- a = e*sinv; asum partials; a' = a*rn split into W buffers as half2 ----
    float ak0 = 0.0f, ak1 = 0.0f;
#pragma unroll
    for (int f = 0; f < 8; ++f) {
        const int p = wn * 64 + f * 8 + 2 * (lane & 3);
        const float s0 = sinv_s[p], s1 = sinv_s[p + 1];
        const float r0 = rn_s[p], r1 = rn_s[p + 1];
        const float a00 = d1[f][0] * s0, a01 = d1[f][1] * s1;
        const float a10 = d1[f][2] * s0, a11 = d1[f][3] * s1;
        ak0 += a00 + a01;
        ak1 += a10 + a11;
        const float q00 = a00 * r0, q01 = a01 * r1;
        const float q10 = a10 * r0, q11 = a11 * r1;
        __half h00 = __float2half_rn(q00), h01 = __float2half_rn(q01);
        __half h10 = __float2half_rn(q10), h11 = __float2half_rn(q11);
        *(__half2*)(sm + W_HI + k0 * RB + p * 2) = __halves2half2(h00, h01);
        *(__half2*)(sm + W_HI + (k0 + 8) * RB + p * 2) = __halves2half2(h10, h11);
        *(__half2*)(sm + W_LO + k0 * RB + p * 2) =
            __halves2half2(__float2half_rn(q00 - __half2float(h00)),
                           __float2half_rn(q01 - __half2float(h01)));
        *(__half2*)(sm + W_LO + (k0 + 8) * RB + p * 2) =
            __halves2half2(__float2half_rn(q10 - __half2float(h10)),
                           __float2half_rn(q11 - __half2float(h11)));
    }
    ak0 += __shfl_xor_sync(0xffffffffu, ak0, 1);
    ak0 += __shfl_xor_sync(0xffffffffu, ak0, 2);
    ak1 += __shfl_xor_sync(0xffffffffu, ak1, 1);
    ak1 += __shfl_xor_sync(0xffffffffu, ak1, 2);
    if ((lane & 3) == 0) {
        asw[w][lane >> 2] = ak0;         // k = wm*16 + (lane>>2)
        asw[w][8 + (lane >> 2)] = ak1;   // k = wm*16 + 8 + (lane>>2)
    }
    __syncthreads();
    if (tid < K) {
        const int wmk = tid >> 4, kk = tid & 15;
        g_asum_part[(n * NTILES + tile) * K + tid] = asw[wmk][kk] + asw[4 + wmk][kk];
    }

    // ---- GEMM2: D2[k][c] = a'[k][p] @ xT[p][c] (trans-B) ----
    float d2[8][4];
#pragma unroll
    for (int f = 0; f < 8; ++f)
#pragma unroll
        for (int e = 0; e < 4; ++e) d2[f][e] = 0.0f;
    __syncthreads();   // a' visible to all warps
    gemm_nt(smb, wm, wn, lane, d2);

    // store partial [k][c]
    {
        float* gp = g_part + (size_t)(n * NTILES + tile) * K * C;
#pragma unroll
        for (int f = 0; f < 8; ++f) {
            const int c = wn * 64 + f * 8 + 2 * (lane & 3);
            *(float2*)(gp + k0 * C + c)       = make_float2(d2[f][0], d2[f][1]);
            *(float2*)(gp + (k0 + 8) * C + c) = make_float2(d2[f][2], d2[f][3]);
        }
    }
}

__global__ __launch_bounds__(256)
void reduce_part() {
    const int n = blockIdx.x;
    const int idx = blockIdx.y * 256 + threadIdx.x;
    const float4* src = (const float4*)g_part + (size_t)n * NTILES * 2048 + idx;
    float4 acc = make_float4(0.f, 0.f, 0.f, 0.f);
#pragma unroll 8
    for (int t = 0; t < NTILES; ++t) {
        float4 v = src[(size_t)t * 2048];
        acc.x += v.x; acc.y += v.y; acc.z += v.z; acc.w += v.w;
    }
    ((float4*)g_vlad)[(size_t)n * 2048 + idx] = acc;
}

__global__ __launch_bounds__(256)
void netvlad_finalize(const float* __restrict__ centroids, float* __restrict__ out) {
    __shared__ float ys[KE * C];
    __shared__ float colss[8 * C];
    __shared__ float colinv[C];
    __shared__ float asl[KE];
    __shared__ float red[8];
    __shared__ float s_inv2;

    const int n = blockIdx.x, tid = threadIdx.x;

    if (tid < KE) {
        float s = 0.0f;
        const float* ap = g_asum_part + (size_t)n * NTILES * K + tid;
#pragma unroll 8
        for (int t = 0; t < NTILES; ++t) s += ap[t * K];
        asl[tid] = s;
    }
    __syncthreads();

    const int cg = (tid & 31) * 4;
    float4 ss4 = make_float4(0.f, 0.f, 0.f, 0.f);
#pragma unroll
    for (int r = 0; r < 7; ++r) {
        int e4 = tid + r * 256;
        int k = e4 >> 5;
        float a = asl[k];
        float4 s = ((const float4*)g_vlad)[(size_t)n * 2048 + k * 32 + (e4 & 31)];
        float4 ce = *(const float4*)(centroids + k * C + cg);
        float4 y;
        y.x = s.x - a * ce.x; y.y = s.y - a * ce.y;
        y.z = s.z - a * ce.z; y.w = s.w - a * ce.w;
        *(float4*)(ys + k * C + cg) = y;
        ss4.x += y.x * y.x; ss4.y += y.y * y.y;
        ss4.z += y.z * y.z; ss4.w += y.w * y.w;
    }
    *(float4*)(colss + (tid >> 5) * C + cg) = ss4;
    __syncthreads();

    float gs = 0.0f;
    if (tid < C) {
        float cs = 0.0f;
#pragma unroll
        for (int g = 0; g < 8; ++g) cs += colss[g * C + tid];
        float i1 = 1.0f / fmaxf(sqrtf(cs), 1e-12f);
        gs = cs * i1 * i1;
        colinv[tid] = i1;
    }
    __syncthreads();
#pragma unroll
    for (int off = 16; off; off >>= 1) gs += __shfl_down_sync(0xffffffffu, gs, off);
    if ((tid & 31) == 0) red[tid >> 5] = gs;
    __syncthreads();
    if (tid == 0) {
        float t = red[0] + red[1] + red[2] + red[3];
        s_inv2 = 1.0f / fmaxf(sqrtf(t), 1e-12f);
    }
    __syncthreads();
    const float inv2 = s_inv2;
    float* op = out + (size_t)n * KE * C;
    for (int idx = tid; idx < KE * C; idx += 256)
        op[idx] = ys[idx] * colinv[idx & 127] * inv2;
}

extern "C" void kernel_launch(void* const* d_in, const int* in_sizes, int n_in,
                              void* d_out, int out_size) {
    const float* x      = (const float*)d_in[0];
    const float* conv_w = (const float*)d_in[1];
    const float* conv_b = (const float*)d_in[2];
    const float* cen    = (const float*)d_in[3];
    float* out = (float*)d_out;

    cudaFuncSetAttribute(netvlad_mma, cudaFuncAttributeMaxDynamicSharedMemorySize, SMEM_DYN);

    netvlad_mma<<<dim3(NB, NTILES), NTHR, SMEM_DYN>>>(x, conv_w, conv_b);
    reduce_part<<<dim3(NB, 8), 256>>>();
    netvlad_finalize<<<NB, 256>>>(cen, out);
}

// round 10
// speedup vs baseline: 2.5000x; 1.1376x over previous
#include <cuda_runtime.h>
#include <cuda_fp16.h>
#include <math.h>
#include <stdint.h>

typedef unsigned long long ull;

#define NB 32
#define C 128
#define HW 4096
#define K 64
#define KE 56
#define TP 128
#define NTILES 32
#define NTHR 256

#define RB 272            // row bytes (136 halfs); 4-bank shift per row

// dynamic smem byte offsets; a' overlays W (W dead after GEMM1)
#define XT_HI 0           // xT[p][c] hi  128*272 = 34816
#define XT_LO 34816
#define W_HI  69632       // W[k][c] hi -> a'[k][p] hi after GEMM1
#define W_LO  87040
#define SMEM_DYN 104448   // 102 KB -> 2 CTAs/SM

__device__ float g_part[NB * NTILES * KE * C];
__device__ float g_asum_part[NB * NTILES * K];
__device__ float g_vlad[NB * KE * C];

__device__ __forceinline__ uint32_t smem_u32(const void* p) {
    uint32_t a;
    asm("{ .reg .u64 t; cvta.to.shared.u64 t, %1; cvt.u32.u64 %0, t; }" : "=r"(a) : "l"(p));
    return a;
}
__device__ __forceinline__ void ldsm_x4(uint32_t a, uint32_t* r) {
    asm volatile("ldmatrix.sync.aligned.m8n8.x4.shared.b16 {%0,%1,%2,%3}, [%4];"
                 : "=r"(r[0]), "=r"(r[1]), "=r"(r[2]), "=r"(r[3]) : "r"(a));
}
__device__ __forceinline__ void ldsm_x4t(uint32_t a, uint32_t* r) {
    asm volatile("ldmatrix.sync.aligned.m8n8.x4.trans.shared.b16 {%0,%1,%2,%3}, [%4];"
                 : "=r"(r[0]), "=r"(r[1]), "=r"(r[2]), "=r"(r[3]) : "r"(a));
}
__device__ __forceinline__ void mma16816(float* d, const uint32_t* a, uint32_t b0, uint32_t b1) {
    asm volatile("mma.sync.aligned.m16n8k16.row.col.f32.f16.f16.f32 "
                 "{%0,%1,%2,%3}, {%4,%5,%6,%7}, {%8,%9}, {%0,%1,%2,%3};"
                 : "+f"(d[0]), "+f"(d[1]), "+f"(d[2]), "+f"(d[3])
                 : "r"(a[0]), "r"(a[1]), "r"(a[2]), "r"(a[3]), "r"(b0), "r"(b1));
}
__device__ __forceinline__ uint32_t h2u(__half2 h) { return *reinterpret_cast<uint32_t*>(&h); }

// GEMM1: A = W[k][c] m32, B = xT[p][c] n32, both row-major [rows][k] -> non-trans
__device__ __forceinline__ void gemm_nn(const uint32_t smb, int wm, int wn, int lane,
                                        float d[8][4]) {
    const uint32_t lo16 = lane & 15;
    const uint32_t sel = (lane >> 4) * 16;
    const uint32_t aOff = (wm * 32 + lo16) * RB + sel;
    const uint32_t bOff = (wn * 32 + lo16) * RB + sel;
#pragma unroll
    for (int ks = 0; ks < 8; ++ks) {
        const uint32_t kb = ks * 32;
        uint32_t ah[8], al[8], bh[8], bl[8];
        ldsm_x4(smb + W_HI + aOff + kb, ah);
        ldsm_x4(smb + W_HI + aOff + 16 * RB + kb, ah + 4);
        ldsm_x4(smb + W_LO + aOff + kb, al);
        ldsm_x4(smb + W_LO + aOff + 16 * RB + kb, al + 4);
        ldsm_x4(smb + XT_HI + bOff + kb, bh);
        ldsm_x4(smb + XT_HI + bOff + 16 * RB + kb, bh + 4);
        ldsm_x4(smb + XT_LO + bOff + kb, bl);
        ldsm_x4(smb + XT_LO + bOff + 16 * RB + kb, bl + 4);
#pragma unroll
        for (int mt = 0; mt < 2; ++mt)
#pragma unroll
            for (int f = 0; f < 4; ++f) {
                const int bi = (f >> 1) * 4 + (f & 1);
                mma16816(d[mt * 4 + f], ah + mt * 4, bh[bi], bh[bi + 2]);
                mma16816(d[mt * 4 + f], al + mt * 4, bh[bi], bh[bi + 2]);
                mma16816(d[mt * 4 + f], ah + mt * 4, bl[bi], bl[bi + 2]);
            }
    }
}

// GEMM2: A = a'[k][p] m32 non-trans (overlaid on W); B = xT[p][c] via trans ldmatrix, n32
__device__ __forceinline__ void gemm_nt(const uint32_t smb, int wm, int wn, int lane,
                                        float d[8][4]) {
    const uint32_t lo16 = lane & 15;
    const uint32_t sel = (lane >> 4) * 16;
    const uint32_t aOff = (wm * 32 + lo16) * RB + sel;
    const uint32_t brow = (lane & 7) + ((lane >> 4) << 3);
    const uint32_t bOff = brow * RB + (wn * 32 + ((lane >> 3) & 1) * 8) * 2;
#pragma unroll
    for (int ks = 0; ks < 8; ++ks) {
        const uint32_t kb = ks * 32;
        const uint32_t bb = ks * 16 * RB;
        uint32_t ah[8], al[8], bh[8], bl[8];
        ldsm_x4(smb + W_HI + aOff + kb, ah);
        ldsm_x4(smb + W_HI + aOff + 16 * RB + kb, ah + 4);
        ldsm_x4(smb + W_LO + aOff + kb, al);
        ldsm_x4(smb + W_LO + aOff + 16 * RB + kb, al + 4);
        ldsm_x4t(smb + XT_HI + bOff + bb, bh);
        ldsm_x4t(smb + XT_HI + bOff + bb + 32, bh + 4);
        ldsm_x4t(smb + XT_LO + bOff + bb, bl);
        ldsm_x4t(smb + XT_LO + bOff + bb + 32, bl + 4);
#pragma unroll
        for (int mt = 0; mt < 2; ++mt)
#pragma unroll
            for (int f = 0; f < 4; ++f) {
                const int bi = (f >> 1) * 4 + (f & 1);
                mma16816(d[mt * 4 + f], ah + mt * 4, bh[bi], bh[bi + 2]);
                mma16816(d[mt * 4 + f], al + mt * 4, bh[bi], bh[bi + 2]);
                mma16816(d[mt * 4 + f], ah + mt * 4, bl[bi], bl[bi + 2]);
            }
    }
}

__global__ __launch_bounds__(NTHR, 2)
void netvlad_mma(const float* __restrict__ x,
                 const float* __restrict__ conv_w,
                 const float* __restrict__ conv_b) {
    extern __shared__ unsigned char sm[];
    const uint32_t smb = smem_u32(sm);

    __shared__ float bs_s[K], rn_s[TP], ms_s[TP], sinv_s[TP];
    __shared__ float red2[2][TP];
    __shared__ float asw[8][32];

    const int n = blockIdx.x, tile = blockIdx.y;
    const int tid = threadIdx.x, lane = tid & 31, w = tid >> 5;
    const int wm = w >> 2, wn = w & 3;   // 2 m-tiles(32) x 4 n-tiles(32)

    // ---- W fp32 -> fp16 hi/lo [k][c], stride RB (packed cvt) ----
    for (int idx = tid; idx < K * C / 2; idx += NTHR) {
        int k = idx >> 6, c2 = (idx & 63) * 2;
        float v0 = __ldg(conv_w + k * C + c2);
        float v1 = __ldg(conv_w + k * C + c2 + 1);
        __half2 h = __float22half2_rn(make_float2(v0, v1));
        float2 hf = __half22float2(h);
        __half2 l = __float22half2_rn(make_float2(v0 - hf.x, v1 - hf.y));
        *(__half2*)(sm + W_HI + k * RB + c2 * 2) = h;
        *(__half2*)(sm + W_LO + k * RB + c2 * 2) = l;
    }
    if (tid < K) bs_s[tid] = conv_b[tid];

    // ---- load x, split fp16 hi/lo into xT[p][c] with STS.128, ssq ----
    {
        const int p = tid & 127, q = tid >> 7;
        const float* xp = x + (size_t)n * C * HW + (size_t)tile * TP + p;
        float ss = 0.0f;
#pragma unroll
        for (int g = 0; g < 8; ++g) {
            const int c = q * 64 + g * 8;
            float v[8];
#pragma unroll
            for (int j = 0; j < 8; ++j) v[j] = __ldg(xp + (size_t)(c + j) * HW);
#pragma unroll
            for (int j = 0; j < 8; ++j) ss += v[j] * v[j];
            uint4 hi, lo;
            {
                __half2 h0 = __float22half2_rn(make_float2(v[0], v[1]));
                __half2 h1 = __float22half2_rn(make_float2(v[2], v[3]));
                __half2 h2 = __float22half2_rn(make_float2(v[4], v[5]));
                __half2 h3 = __float22half2_rn(make_float2(v[6], v[7]));
                hi = make_uint4(h2u(h0), h2u(h1), h2u(h2), h2u(h3));
                float2 f0 = __half22float2(h0), f1 = __half22float2(h1);
                float2 f2 = __half22float2(h2), f3 = __half22float2(h3);
                lo = make_uint4(
                    h2u(__float22half2_rn(make_float2(v[0] - f0.x, v[1] - f0.y))),
                    h2u(__float22half2_rn(make_float2(v[2] - f1.x, v[3] - f1.y))),
                    h2u(__float22half2_rn(make_float2(v[4] - f2.x, v[5] - f2.y))),
                    h2u(__float22half2_rn(make_float2(v[6] - f3.x, v[7] - f3.y))));
            }
            *(uint4*)(sm + XT_HI + p * RB + c * 2) = hi;
            *(uint4*)(sm + XT_LO + p * RB + c * 2) = lo;
        }
        red2[q][p] = ss;
    }
    __syncthreads();
    if (tid < TP)
        rn_s[tid] = 1.0f / fmaxf(sqrtf(red2[0][tid] + red2[1][tid]), 1e-12f);
    __syncthreads();

    // ---- GEMM1: D1[k][p], warp = m32 x n32 ----
    float d1[8][4];
#pragma unroll
    for (int f = 0; f < 8; ++f)
#pragma unroll
        for (int e = 0; e < 4; ++e) d1[f][e] = 0.0f;
    gemm_nn(smb, wm, wn, lane, d1);

    // ---- logits + softmax (registers + shfl + 2-deep smem reduce) ----
    const int k0 = wm * 32 + (lane >> 2);   // rows: k0 + 16*mt + {0,8}
    float bk[4] = {bs_s[k0], bs_s[k0 + 8], bs_s[k0 + 16], bs_s[k0 + 24]};
#pragma unroll
    for (int mt = 0; mt < 2; ++mt)
#pragma unroll
        for (int f = 0; f < 4; ++f) {
            const int p = wn * 32 + f * 8 + 2 * (lane & 3);
            const float r0 = rn_s[p], r1 = rn_s[p + 1];
            float* dd = d1[mt * 4 + f];
            dd[0] = dd[0] * r0 + bk[2 * mt];
            dd[1] = dd[1] * r1 + bk[2 * mt];
            dd[2] = dd[2] * r0 + bk[2 * mt + 1];
            dd[3] = dd[3] * r1 + bk[2 * mt + 1];
        }
    // per-pixel max over this warp's 32 k
#pragma unroll
    for (int f = 0; f < 4; ++f) {
        float m0 = fmaxf(fmaxf(d1[f][0], d1[f][2]), fmaxf(d1[4 + f][0], d1[4 + f][2]));
        float m1 = fmaxf(fmaxf(d1[f][1], d1[f][3]), fmaxf(d1[4 + f][1], d1[4 + f][3]));
#pragma unroll
        for (int off = 4; off <= 16; off <<= 1) {
            m0 = fmaxf(m0, __shfl_xor_sync(0xffffffffu, m0, off));
            m1 = fmaxf(m1, __shfl_xor_sync(0xffffffffu, m1, off));
        }
        if ((lane >> 2) == 0) {
            const int p = wn * 32 + f * 8 + 2 * lane;
            red2[wm][p] = m0;
            red2[wm][p + 1] = m1;
        }
    }
    __syncthreads();
    if (tid < TP) ms_s[tid] = fmaxf(red2[0][tid], red2[1][tid]);
    __syncthreads();

#pragma unroll
    for (int f = 0; f < 4; ++f) {
        const int p = wn * 32 + f * 8 + 2 * (lane & 3);
        const float M0 = ms_s[p], M1 = ms_s[p + 1];
#pragma unroll
        for (int mt = 0; mt < 2; ++mt) {
            float* dd = d1[mt * 4 + f];
            dd[0] = __expf(dd[0] - M0);
            dd[1] = __expf(dd[1] - M1);
            dd[2] = __expf(dd[2] - M0);
            dd[3] = __expf(dd[3] - M1);
        }
        float s0 = d1[f][0] + d1[f][2] + d1[4 + f][0] + d1[4 + f][2];
        float s1 = d1[f][1] + d1[f][3] + d1[4 + f][1] + d1[4 + f][3];
#pragma unroll
        for (int off = 4; off <= 16; off <<= 1) {
            s0 += __shfl_xor_sync(0xffffffffu, s0, off);
            s1 += __shfl_xor_sync(0xffffffffu, s1, off);
        }
        if ((lane >> 2) == 0) {
            const int p2 = wn * 32 + f * 8 + 2 * lane;
            red2[wm][p2] = s0;
            red2[wm][p2 + 1] = s1;
        }
    }
    __syncthreads();
    if (tid < TP) sinv_s[tid] = 1.0f / (red2[0][tid] + red2[1][tid]);
    __syncthreads();   // all warps past GEMM1: W region dead, overlay a'

    // ---- a = e*sinv; asum; a' = a*rn hi/lo into W region ----
    float aks[4] = {0.f, 0.f, 0.f, 0.f};   // per-thread row sums: rows k0+16mt+8e
#pragma unroll
    for (int mt = 0; mt < 2; ++mt)
#pragma unroll
        for (int f = 0; f < 4; ++f) {
            const int p = wn * 32 + f * 8 + 2 * (lane & 3);
            const float s0 = sinv_s[p], s1 = sinv_s[p + 1];
            const float r0 = rn_s[p], r1 = rn_s[p + 1];
            float* dd = d1[mt * 4 + f];
            const float a00 = dd[0] * s0, a01 = dd[1] * s1;
            const float a10 = dd[2] * s0, a11 = dd[3] * s1;
            aks[2 * mt] += a00 + a01;
            aks[2 * mt + 1] += a10 + a11;
            __half2 h0 = __float22half2_rn(make_float2(a00 * r0, a01 * r1));
            __half2 h1 = __float22half2_rn(make_float2(a10 * r0, a11 * r1));
            float2 f0 = __half22float2(h0), f1 = __half22float2(h1);
            __half2 l0 = __float22half2_rn(make_float2(a00 * r0 - f0.x, a01 * r1 - f0.y));
            __half2 l1 = __float22half2_rn(make_float2(a10 * r0 - f1.x, a11 * r1 - f1.y));
            const int kr = k0 + 16 * mt;
            *(__half2*)(sm + W_HI + kr * RB + p * 2) = h0;
            *(__half2*)(sm + W_HI + (kr + 8) * RB + p * 2) = h1;
            *(__half2*)(sm + W_LO + kr * RB + p * 2) = l0;
            *(__half2*)(sm + W_LO + (kr + 8) * RB + p * 2) = l1;
        }
#pragma unroll
    for (int i = 0; i < 4; ++i) {
        aks[i] += __shfl_xor_sync(0xffffffffu, aks[i], 1);
        aks[i] += __shfl_xor_sync(0xffffffffu, aks[i], 2);
    }
    if ((lane & 3) == 0) {
        const int r = lane >> 2;
        asw[w][r] = aks[0];
        asw[w][8 + r] = aks[1];
        asw[w][16 + r] = aks[2];
        asw[w][24 + r] = aks[3];
    }
    __syncthreads();   // a' + asw visible
    if (tid < K) {
        const int wmk = tid >> 5, kk = tid & 31;
        g_asum_part[(n * NTILES + tile) * K + tid] =
            asw[wmk * 4 + 0][kk] + asw[wmk * 4 + 1][kk] +
            asw[wmk * 4 + 2][kk] + asw[wmk * 4 + 3][kk];
    }

    // ---- GEMM2: D2[k][c] = a'[k][p] @ xT[p][c] (trans-B) ----
    float d2[8][4];
#pragma unroll
    for (int f = 0; f < 8; ++f)
#pragma unroll
        for (int e = 0; e < 4; ++e) d2[f][e] = 0.0f;
    gemm_nt(smb, wm, wn, lane, d2);

    // store partial [k][c], k < KE only
    {
        float* gp = g_part + (size_t)(n * NTILES + tile) * KE * C;
#pragma unroll
        for (int mt = 0; mt < 2; ++mt)
#pragma unroll
            for (int f = 0; f < 4; ++f) {
                const int c = wn * 32 + f * 8 + 2 * (lane & 3);
                const int kr = k0 + 16 * mt;
                float* dd = d2[mt * 4 + f];
                *(float2*)(gp + kr * C + c) = make_float2(dd[0], dd[1]);
                if (kr + 8 < KE)
                    *(float2*)(gp + (kr + 8) * C + c) = make_float2(dd[2], dd[3]);
            }
    }
}

__global__ __launch_bounds__(256)
void reduce_part() {
    const int n = blockIdx.x;
    const int idx = blockIdx.y * 256 + threadIdx.x;   // 0..1791 float4 units (KE*C/4)
    const float4* src = (const float4*)g_part + (size_t)n * NTILES * 1792 + idx;
    float4 acc = make_float4(0.f, 0.f, 0.f, 0.f);
#pragma unroll 8
    for (int t = 0; t < NTILES; ++t) {
        float4 v = src[(size_t)t * 1792];
        acc.x += v.x; acc.y += v.y; acc.z += v.z; acc.w += v.w;
    }
    ((float4*)g_vlad)[(size_t)n * 1792 + idx] = acc;
}

__global__ __launch_bounds__(256)
void netvlad_finalize(const float* __restrict__ centroids, float* __restrict__ out) {
    __shared__ float ys[KE * C];
    __shared__ float colss[8 * C];
    __shared__ float colinv[C];
    __shared__ float asl[KE];
    __shared__ float red[8];
    __shared__ float s_inv2;

    const int n = blockIdx.x, tid = threadIdx.x;

    if (tid < KE) {
        float s = 0.0f;
        const float* ap = g_asum_part + (size_t)n * NTILES * K + tid;
#pragma unroll 8
        for (int t = 0; t < NTILES; ++t) s += ap[t * K];
        asl[tid] = s;
    }
    __syncthreads();

    const int cg = (tid & 31) * 4;
    float4 ss4 = make_float4(0.f, 0.f, 0.f, 0.f);
#pragma unroll
    for (int r = 0; r < 7; ++r) {
        int e4 = tid + r * 256;
        int k = e4 >> 5;
        float a = asl[k];
        float4 s = ((const float4*)g_vlad)[(size_t)n * 1792 + e4];
        float4 ce = *(const float4*)(centroids + k * C + cg);
        float4 y;
        y.x = s.x - a * ce.x; y.y = s.y - a * ce.y;
        y.z = s.z - a * ce.z; y.w = s.w - a * ce.w;
        *(float4*)(ys + k * C + cg) = y;
        ss4.x += y.x * y.x; ss4.y += y.y * y.y;
        ss4.z += y.z * y.z; ss4.w += y.w * y.w;
    }
    *(float4*)(colss + (tid >> 5) * C + cg) = ss4;
    __syncthreads();

    float gs = 0.0f;
    if (tid < C) {
        float cs = 0.0f;
#pragma unroll
        for (int g = 0; g < 8; ++g) cs += colss[g * C + tid];
        float i1 = 1.0f / fmaxf(sqrtf(cs), 1e-12f);
        gs = cs * i1 * i1;
        colinv[tid] = i1;
    }
    __syncthreads();
#pragma unroll
    for (int off = 16; off; off >>= 1) gs += __shfl_down_sync(0xffffffffu, gs, off);
    if ((tid & 31) == 0) red[tid >> 5] = gs;
    __syncthreads();
    if (tid == 0) {
        float t = red[0] + red[1] + red[2] + red[3];
        s_inv2 = 1.0f / fmaxf(sqrtf(t), 1e-12f);
    }
    __syncthreads();
    const float inv2 = s_inv2;
    float* op = out + (size_t)n * KE * C;
    for (int idx = tid; idx < KE * C; idx += 256)
        op[idx] = ys[idx] * colinv[idx & 127] * inv2;
}

extern "C" void kernel_launch(void* const* d_in, const int* in_sizes, int n_in,
                              void* d_out, int out_size) {
    const float* x      = (const float*)d_in[0];
    const float* conv_w = (const float*)d_in[1];
    const float* conv_b = (const float*)d_in[2];
    const float* cen    = (const float*)d_in[3];
    float* out = (float*)d_out;

    cudaFuncSetAttribute(netvlad_mma, cudaFuncAttributeMaxDynamicSharedMemorySize, SMEM_DYN);

    netvlad_mma<<<dim3(NB, NTILES), NTHR, SMEM_DYN>>>(x, conv_w, conv_b);
    reduce_part<<<dim3(NB, 7), 256>>>();
    netvlad_finalize<<<NB, 256>>>(cen, out);
}

// round 11
// speedup vs baseline: 2.9938x; 1.1975x over previous
#include <cuda_runtime.h>
#include <cuda_fp16.h>
#include <math.h>
#include <stdint.h>

typedef unsigned long long ull;

#define NB 32
#define C 128
#define HW 4096
#define K 64
#define KE 56
#define TP 128
#define NTILES 32
#define NTHR 256

#define RB 272            // row bytes (136 halfs); 4-bank shift per row

// dynamic smem byte offsets; a' overlays W_HI (W dead after GEMM1)
#define XT_HI 0           // xT[p][c] hi  128*272 = 34816
#define XT_LO 34816
#define W_HI  69632       // W[k][c] hi -> a'[k][p] hi after GEMM1
#define W_LO  87040
#define SMEM_DYN 104448   // 102 KB -> 2 CTAs/SM

__device__ float g_part[NB * NTILES * KE * C];
__device__ float g_asum_part[NB * NTILES * K];
__device__ float g_vlad[NB * KE * C];
__device__ __align__(16) unsigned char g_wh[K * RB];   // pre-swizzled W fp16 hi image
__device__ __align__(16) unsigned char g_wl[K * RB];   // lo image

__device__ __forceinline__ uint32_t smem_u32(const void* p) {
    uint32_t a;
    asm("{ .reg .u64 t; cvta.to.shared.u64 t, %1; cvt.u32.u64 %0, t; }" : "=r"(a) : "l"(p));
    return a;
}
__device__ __forceinline__ void ldsm_x4(uint32_t a, uint32_t* r) {
    asm volatile("ldmatrix.sync.aligned.m8n8.x4.shared.b16 {%0,%1,%2,%3}, [%4];"
                 : "=r"(r[0]), "=r"(r[1]), "=r"(r[2]), "=r"(r[3]) : "r"(a));
}
__device__ __forceinline__ void ldsm_x4t(uint32_t a, uint32_t* r) {
    asm volatile("ldmatrix.sync.aligned.m8n8.x4.trans.shared.b16 {%0,%1,%2,%3}, [%4];"
                 : "=r"(r[0]), "=r"(r[1]), "=r"(r[2]), "=r"(r[3]) : "r"(a));
}
__device__ __forceinline__ void mma16816(float* d, const uint32_t* a, uint32_t b0, uint32_t b1) {
    asm volatile("mma.sync.aligned.m16n8k16.row.col.f32.f16.f16.f32 "
                 "{%0,%1,%2,%3}, {%4,%5,%6,%7}, {%8,%9}, {%0,%1,%2,%3};"
                 : "+f"(d[0]), "+f"(d[1]), "+f"(d[2]), "+f"(d[3])
                 : "r"(a[0]), "r"(a[1]), "r"(a[2]), "r"(a[3]), "r"(b0), "r"(b1));
}
__device__ __forceinline__ uint32_t h2u(__half2 h) { return *reinterpret_cast<uint32_t*>(&h); }

// prep: W fp32 -> fp16 hi/lo in final [k][RB] smem image (done once per launch)
__global__ void prep_w(const float* __restrict__ conv_w) {
    int idx = blockIdx.x * blockDim.x + threadIdx.x;
    if (idx < K * C / 2) {
        int k = idx >> 6, c2 = (idx & 63) * 2;
        float v0 = __ldg(conv_w + k * C + c2);
        float v1 = __ldg(conv_w + k * C + c2 + 1);
        __half2 h = __float22half2_rn(make_float2(v0, v1));
        float2 hf = __half22float2(h);
        __half2 l = __float22half2_rn(make_float2(v0 - hf.x, v1 - hf.y));
        *(__half2*)(g_wh + k * RB + c2 * 2) = h;
        *(__half2*)(g_wl + k * RB + c2 * 2) = l;
    }
}

// GEMM1: A = W[k][c] m32, B = xT[p][c] n32, both row-major [rows][k] -> non-trans.
// 3 split passes: hi*hi + lo*hi + hi*lo (full precision needed: alpha=100 amplifies).
__device__ __forceinline__ void gemm_nn(const uint32_t smb, int wm, int wn, int lane,
                                        float d[8][4]) {
    const uint32_t lo16 = lane & 15;
    const uint32_t sel = (lane >> 4) * 16;
    const uint32_t aOff = (wm * 32 + lo16) * RB + sel;
    const uint32_t bOff = (wn * 32 + lo16) * RB + sel;
#pragma unroll
    for (int ks = 0; ks < 8; ++ks) {
        const uint32_t kb = ks * 32;
        uint32_t ah[8], al[8], bh[8], bl[8];
        ldsm_x4(smb + W_HI + aOff + kb, ah);
        ldsm_x4(smb + W_HI + aOff + 16 * RB + kb, ah + 4);
        ldsm_x4(smb + W_LO + aOff + kb, al);
        ldsm_x4(smb + W_LO + aOff + 16 * RB + kb, al + 4);
        ldsm_x4(smb + XT_HI + bOff + kb, bh);
        ldsm_x4(smb + XT_HI + bOff + 16 * RB + kb, bh + 4);
        ldsm_x4(smb + XT_LO + bOff + kb, bl);
        ldsm_x4(smb + XT_LO + bOff + 16 * RB + kb, bl + 4);
#pragma unroll
        for (int mt = 0; mt < 2; ++mt)
#pragma unroll
            for (int f = 0; f < 4; ++f) {
                const int bi = (f >> 1) * 4 + (f & 1);
                mma16816(d[mt * 4 + f], ah + mt * 4, bh[bi], bh[bi + 2]);
                mma16816(d[mt * 4 + f], al + mt * 4, bh[bi], bh[bi + 2]);
                mma16816(d[mt * 4 + f], ah + mt * 4, bl[bi], bl[bi + 2]);
            }
    }
}

// GEMM2: single hi*hi pass (error lands on the small Sum(a*xn) term; asum*c is exact fp32).
// A = a'[k][p] m32 non-trans (overlaid on W_HI); B = xT[p][c] hi via trans ldmatrix, n32.
__device__ __forceinline__ void gemm_nt(const uint32_t smb, int wm, int wn, int lane,
                                        float d[8][4]) {
    const uint32_t lo16 = lane & 15;
    const uint32_t sel = (lane >> 4) * 16;
    const uint32_t aOff = (wm * 32 + lo16) * RB + sel;
    const uint32_t brow = (lane & 7) + ((lane >> 4) << 3);
    const uint32_t bOff = brow * RB + (wn * 32 + ((lane >> 3) & 1) * 8) * 2;
#pragma unroll
    for (int ks = 0; ks < 8; ++ks) {
        const uint32_t kb = ks * 32;
        const uint32_t bb = ks * 16 * RB;
        uint32_t ah[8], bh[8];
        ldsm_x4(smb + W_HI + aOff + kb, ah);
        ldsm_x4(smb + W_HI + aOff + 16 * RB + kb, ah + 4);
        ldsm_x4t(smb + XT_HI + bOff + bb, bh);
        ldsm_x4t(smb + XT_HI + bOff + bb + 32, bh + 4);
#pragma unroll
        for (int mt = 0; mt < 2; ++mt)
#pragma unroll
            for (int f = 0; f < 4; ++f) {
                const int bi = (f >> 1) * 4 + (f & 1);
                mma16816(d[mt * 4 + f], ah + mt * 4, bh[bi], bh[bi + 2]);
            }
    }
}

__global__ __launch_bounds__(NTHR, 2)
void netvlad_mma(const float* __restrict__ x,
                 const float* __restrict__ conv_b) {
    extern __shared__ unsigned char sm[];
    const uint32_t smb = smem_u32(sm);

    __shared__ float bs_s[K], rn_s[TP], ms_s[TP], sinv_s[TP];
    __shared__ float red2[2][TP];
    __shared__ float asw[8][32];

    const int n = blockIdx.x, tile = blockIdx.y;
    const int tid = threadIdx.x, lane = tid & 31, w = tid >> 5;
    const int wm = w >> 2, wn = w & 3;   // 2 m-tiles(32) x 4 n-tiles(32)

    // ---- copy pre-converted W images (uint4) ----
    {
        const uint4* s1 = (const uint4*)g_wh;
        const uint4* s2 = (const uint4*)g_wl;
        uint4* d1 = (uint4*)(sm + W_HI);
        uint4* d2 = (uint4*)(sm + W_LO);
        for (int i = tid; i < K * RB / 16; i += NTHR) { d1[i] = s1[i]; d2[i] = s2[i]; }
    }
    if (tid < K) bs_s[tid] = conv_b[tid];

    // ---- load x, split fp16 hi/lo into xT[p][c] with STS.128, ssq ----
    {
        const int p = tid & 127, q = tid >> 7;
        const float* xp = x + (size_t)n * C * HW + (size_t)tile * TP + p;
        float ss = 0.0f;
#pragma unroll
        for (int g = 0; g < 8; ++g) {
            const int c = q * 64 + g * 8;
            float v[8];
#pragma unroll
            for (int j = 0; j < 8; ++j) v[j] = __ldg(xp + (size_t)(c + j) * HW);
#pragma unroll
            for (int j = 0; j < 8; ++j) ss += v[j] * v[j];
            uint4 hi, lo;
            {
                __half2 h0 = __float22half2_rn(make_float2(v[0], v[1]));
                __half2 h1 = __float22half2_rn(make_float2(v[2], v[3]));
                __half2 h2 = __float22half2_rn(make_float2(v[4], v[5]));
                __half2 h3 = __float22half2_rn(make_float2(v[6], v[7]));
                hi = make_uint4(h2u(h0), h2u(h1), h2u(h2), h2u(h3));
                float2 f0 = __half22float2(h0), f1 = __half22float2(h1);
                float2 f2 = __half22float2(h2), f3 = __half22float2(h3);
                lo = make_uint4(
                    h2u(__float22half2_rn(make_float2(v[0] - f0.x, v[1] - f0.y))),
                    h2u(__float22half2_rn(make_float2(v[2] - f1.x, v[3] - f1.y))),
                    h2u(__float22half2_rn(make_float2(v[4] - f2.x, v[5] - f2.y))),
                    h2u(__float22half2_rn(make_float2(v[6] - f3.x, v[7] - f3.y))));
            }
            *(uint4*)(sm + XT_HI + p * RB + c * 2) = hi;
            *(uint4*)(sm + XT_LO + p * RB + c * 2) = lo;
        }
        red2[q][p] = ss;
    }
    __syncthreads();
    if (tid < TP)
        rn_s[tid] = 1.0f / fmaxf(sqrtf(red2[0][tid] + red2[1][tid]), 1e-12f);
    __syncthreads();

    // ---- GEMM1: D1[k][p], warp = m32 x n32, 3 passes ----
    float d1[8][4];
#pragma unroll
    for (int f = 0; f < 8; ++f)
#pragma unroll
        for (int e = 0; e < 4; ++e) d1[f][e] = 0.0f;
    gemm_nn(smb, wm, wn, lane, d1);

    // ---- logits + softmax (registers + shfl + 2-deep smem reduce) ----
    const int k0 = wm * 32 + (lane >> 2);
    float bk[4] = {bs_s[k0], bs_s[k0 + 8], bs_s[k0 + 16], bs_s[k0 + 24]};
#pragma unroll
    for (int mt = 0; mt < 2; ++mt)
#pragma unroll
        for (int f = 0; f < 4; ++f) {
            const int p = wn * 32 + f * 8 + 2 * (lane & 3);
            const float r0 = rn_s[p], r1 = rn_s[p + 1];
            float* dd = d1[mt * 4 + f];
            dd[0] = dd[0] * r0 + bk[2 * mt];
            dd[1] = dd[1] * r1 + bk[2 * mt];
            dd[2] = dd[2] * r0 + bk[2 * mt + 1];
            dd[3] = dd[3] * r1 + bk[2 * mt + 1];
        }
#pragma unroll
    for (int f = 0; f < 4; ++f) {
        float m0 = fmaxf(fmaxf(d1[f][0], d1[f][2]), fmaxf(d1[4 + f][0], d1[4 + f][2]));
        float m1 = fmaxf(fmaxf(d1[f][1], d1[f][3]), fmaxf(d1[4 + f][1], d1[4 + f][3]));
#pragma unroll
        for (int off = 4; off <= 16; off <<= 1) {
            m0 = fmaxf(m0, __shfl_xor_sync(0xffffffffu, m0, off));
            m1 = fmaxf(m1, __shfl_xor_sync(0xffffffffu, m1, off));
        }
        if ((lane >> 2) == 0) {
            const int p = wn * 32 + f * 8 + 2 * lane;
            red2[wm][p] = m0;
            red2[wm][p + 1] = m1;
        }
    }
    __syncthreads();
    if (tid < TP) ms_s[tid] = fmaxf(red2[0][tid], red2[1][tid]);
    __syncthreads();

#pragma unroll
    for (int f = 0; f < 4; ++f) {
        const int p = wn * 32 + f * 8 + 2 * (lane & 3);
        const float M0 = ms_s[p], M1 = ms_s[p + 1];
#pragma unroll
        for (int mt = 0; mt < 2; ++mt) {
            float* dd = d1[mt * 4 + f];
            dd[0] = __expf(dd[0] - M0);
            dd[1] = __expf(dd[1] - M1);
            dd[2] = __expf(dd[2] - M0);
            dd[3] = __expf(dd[3] - M1);
        }
        float s0 = d1[f][0] + d1[f][2] + d1[4 + f][0] + d1[4 + f][2];
        float s1 = d1[f][1] + d1[f][3] + d1[4 + f][1] + d1[4 + f][3];
#pragma unroll
        for (int off = 4; off <= 16; off <<= 1) {
            s0 += __shfl_xor_sync(0xffffffffu, s0, off);
            s1 += __shfl_xor_sync(0xffffffffu, s1, off);
        }
        if ((lane >> 2) == 0) {
            const int p2 = wn * 32 + f * 8 + 2 * lane;
            red2[wm][p2] = s0;
            red2[wm][p2 + 1] = s1;
        }
    }
    __syncthreads();
    if (tid < TP) sinv_s[tid] = 1.0f / (red2[0][tid] + red2[1][tid]);
    __syncthreads();   // all warps past GEMM1: W_HI region dead, overlay a'

    // ---- a = e*sinv; asum; a' = a*rn (hi only) into W_HI region ----
    float aks[4] = {0.f, 0.f, 0.f, 0.f};
#pragma unroll
    for (int mt = 0; mt < 2; ++mt)
#pragma unroll
        for (int f = 0; f < 4; ++f) {
            const int p = wn * 32 + f * 8 + 2 * (lane & 3);
            const float s0 = sinv_s[p], s1 = sinv_s[p + 1];
            const float r0 = rn_s[p], r1 = rn_s[p + 1];
            float* dd = d1[mt * 4 + f];
            const float a00 = dd[0] * s0, a01 = dd[1] * s1;
            const float a10 = dd[2] * s0, a11 = dd[3] * s1;
            aks[2 * mt] += a00 + a01;
            aks[2 * mt + 1] += a10 + a11;
            __half2 h0 = __float22half2_rn(make_float2(a00 * r0, a01 * r1));
            __half2 h1 = __float22half2_rn(make_float2(a10 * r0, a11 * r1));
            const int kr = k0 + 16 * mt;
            *(__half2*)(sm + W_HI + kr * RB + p * 2) = h0;
            *(__half2*)(sm + W_HI + (kr + 8) * RB + p * 2) = h1;
        }
#pragma unroll
    for (int i = 0; i < 4; ++i) {
        aks[i] += __shfl_xor_sync(0xffffffffu, aks[i], 1);
        aks[i] += __shfl_xor_sync(0xffffffffu, aks[i], 2);
    }
    if ((lane & 3) == 0) {
        const int r = lane >> 2;
        asw[w][r] = aks[0];
        asw[w][8 + r] = aks[1];
        asw[w][16 + r] = aks[2];
        asw[w][24 + r] = aks[3];
    }
    __syncthreads();
    if (tid < K) {
        const int wmk = tid >> 5, kk = tid & 31;
        g_asum_part[(n * NTILES + tile) * K + tid] =
            asw[wmk * 4 + 0][kk] + asw[wmk * 4 + 1][kk] +
            asw[wmk * 4 + 2][kk] + asw[wmk * 4 + 3][kk];
    }

    // ---- GEMM2: D2[k][c] = a'[k][p] @ xT_hi[p][c] (trans-B, single pass) ----
    float d2[8][4];
#pragma unroll
    for (int f = 0; f < 8; ++f)
#pragma unroll
        for (int e = 0; e < 4; ++e) d2[f][e] = 0.0f;
    gemm_nt(smb, wm, wn, lane, d2);

    // store partial [k][c], k < KE only
    {
        float* gp = g_part + (size_t)(n * NTILES + tile) * KE * C;
#pragma unroll
        for (int mt = 0; mt < 2; ++mt)
#pragma unroll
            for (int f = 0; f < 4; ++f) {
                const int c = wn * 32 + f * 8 + 2 * (lane & 3);
                const int kr = k0 + 16 * mt;
                float* dd = d2[mt * 4 + f];
                *(float2*)(gp + kr * C + c) = make_float2(dd[0], dd[1]);
                if (kr + 8 < KE)
                    *(float2*)(gp + (kr + 8) * C + c) = make_float2(dd[2], dd[3]);
            }
    }
}

__global__ __launch_bounds__(256)
void reduce_part() {
    const int n = blockIdx.x;
    const int idx = blockIdx.y * 256 + threadIdx.x;   // 0..1791 float4 units (KE*C/4)
    const float4* src = (const float4*)g_part + (size_t)n * NTILES * 1792 + idx;
    float4 acc = make_float4(0.f, 0.f, 0.f, 0.f);
#pragma unroll 8
    for (int t = 0; t < NTILES; ++t) {
        float4 v = src[(size_t)t * 1792];
        acc.x += v.x; acc.y += v.y; acc.z += v.z; acc.w += v.w;
    }
    ((float4*)g_vlad)[(size_t)n * 1792 + idx] = acc;
}

__global__ __launch_bounds__(256)
void netvlad_finalize(const float* __restrict__ centroids, float* __restrict__ out) {
    __shared__ float ys[KE * C];
    __shared__ float colss[8 * C];
    __shared__ float colinv[C];
    __shared__ float asl[KE];
    __shared__ float red[8];
    __shared__ float s_inv2;

    const int n = blockIdx.x, tid = threadIdx.x;

    if (tid < KE) {
        float s = 0.0f;
        const float* ap = g_asum_part + (size_t)n * NTILES * K + tid;
#pragma unroll 8
        for (int t = 0; t < NTILES; ++t) s += ap[t * K];
        asl[tid] = s;
    }
    __syncthreads();

    const int cg = (tid & 31) * 4;
    float4 ss4 = make_float4(0.f, 0.f, 0.f, 0.f);
#pragma unroll
    for (int r = 0; r < 7; ++r) {
        int e4 = tid + r * 256;
        int k = e4 >> 5;
        float a = asl[k];
        float4 s = ((const float4*)g_vlad)[(size_t)n * 1792 + e4];
        float4 ce = *(const float4*)(centroids + k * C + cg);
        float4 y;
        y.x = s.x - a * ce.x; y.y = s.y - a * ce.y;
        y.z = s.z - a * ce.z; y.w = s.w - a * ce.w;
        *(float4*)(ys + k * C + cg) = y;
        ss4.x += y.x * y.x; ss4.y += y.y * y.y;
        ss4.z += y.z * y.z; ss4.w += y.w * y.w;
    }
    *(float4*)(colss + (tid >> 5) * C + cg) = ss4;
    __syncthreads();

    float gs = 0.0f;
    if (tid < C) {
        float cs = 0.0f;
#pragma unroll
        for (int g = 0; g < 8; ++g) cs += colss[g * C + tid];
        float i1 = 1.0f / fmaxf(sqrtf(cs), 1e-12f);
        gs = cs * i1 * i1;
        colinv[tid] = i1;
    }
    __syncthreads();
#pragma unroll
    for (int off = 16; off; off >>= 1) gs += __shfl_down_sync(0xffffffffu, gs, off);
    if ((tid & 31) == 0) red[tid >> 5] = gs;
    __syncthreads();
    if (tid == 0) {
        float t = red[0] + red[1] + red[2] + red[3];
        s_inv2 = 1.0f / fmaxf(sqrtf(t), 1e-12f);
    }
    __syncthreads();
    const float inv2 = s_inv2;
    float* op = out + (size_t)n * KE * C;
    for (int idx = tid; idx < KE * C; idx += 256)
        op[idx] = ys[idx] * colinv[idx & 127] * inv2;
}

extern "C" void kernel_launch(void* const* d_in, const int* in_sizes, int n_in,
                              void* d_out, int out_size) {
    const float* x      = (const float*)d_in[0];
    const float* conv_w = (const float*)d_in[1];
    const float* conv_b = (const float*)d_in[2];
    const float* cen    = (const float*)d_in[3];
    float* out = (float*)d_out;

    cudaFuncSetAttribute(netvlad_mma, cudaFuncAttributeMaxDynamicSharedMemorySize, SMEM_DYN);

    prep_w<<<16, 256>>>(conv_w);
    netvlad_mma<<<dim3(NB, NTILES), NTHR, SMEM_DYN>>>(x, conv_b);
    reduce_part<<<dim3(NB, 7), 256>>>();
    netvlad_finalize<<<NB, 256>>>(cen, out);
}